// round 7
// baseline (speedup 1.0000x reference)
#include <cuda_runtime.h>
#include <math.h>

// ---------------------------------------------------------------------------
// Problem constants
// ---------------------------------------------------------------------------
#define Bb   4
#define Tt   1024
#define Dd   1024
#define Hh   16
#define DK   64
#define DV   64
#define II   2816
#define EPSf 1e-6f
#define ROWS (Bb*Tt)              // 4096

// ---------------------------------------------------------------------------
// Scratch (static device memory; no allocations allowed)
// ---------------------------------------------------------------------------
__device__ float g_h   [ROWS*Dd];      // rmsnorm(x)
__device__ float g_qpre[ROWS*Dd];
__device__ float g_kpre[ROWS*Dd];
__device__ float g_vpre[ROWS*Dd];
__device__ float g_q   [ROWS*Dd];
__device__ float g_k   [ROWS*Dd];
__device__ float g_v   [ROWS*Dd];
__device__ float g_beta[ROWS*Hh];
__device__ float g_g   [ROWS*Hh];
__device__ float g_o   [ROWS*Dd];      // attn output per head
__device__ float g_h2  [ROWS*Dd];      // x + attn_out
__device__ float g_h3  [ROWS*Dd];      // rmsnorm(h2)
__device__ float g_gy  [ROWS*2*II];    // h3 @ Wg

// ---------------------------------------------------------------------------
// RMSNorm over D=1024, one block (256 thr) per row
// ---------------------------------------------------------------------------
__global__ void rmsnorm_kernel(const float* __restrict__ x, const float* __restrict__ w,
                               float* __restrict__ out) {
    int row = blockIdx.x;
    const float4* xr = (const float4*)(x + (size_t)row * Dd);
    float4 v = xr[threadIdx.x];
    float ss = v.x*v.x + v.y*v.y + v.z*v.z + v.w*v.w;
    #pragma unroll
    for (int m = 16; m >= 1; m >>= 1) ss += __shfl_xor_sync(0xffffffffu, ss, m);
    __shared__ float wsum[8];
    if ((threadIdx.x & 31) == 0) wsum[threadIdx.x >> 5] = ss;
    __syncthreads();
    float tot = wsum[0]+wsum[1]+wsum[2]+wsum[3]+wsum[4]+wsum[5]+wsum[6]+wsum[7];
    float r = rsqrtf(tot * (1.0f/Dd) + EPSf);
    float4 wv = ((const float4*)w)[threadIdx.x];
    float4 o;
    o.x = v.x*r*wv.x; o.y = v.y*r*wv.y; o.z = v.z*r*wv.z; o.w = v.w*r*wv.w;
    ((float4*)(out + (size_t)row * Dd))[threadIdx.x] = o;
}

// ---------------------------------------------------------------------------
// TF32 tensor-core GEMM: C[M,N] = A[M,K] @ B[K,N] (+addsrc)
// BM=128 BN=128 BK=16, 256 threads (8 warps, 2x4), warp tile 64x32,
// mma.sync.m16n8k8.tf32, double-buffered static smem (34.3KB -> 2 CTAs/SM).
// Fragment-permuted smem: A fragment = 1 LDS.128, B fragment = 1 LDS.64.
// FUSE_SWIGLU: A is gy [M, 2*II]; staged value = silu(gate)*y.
// ---------------------------------------------------------------------------
#define GBM 128
#define GBN 128
#define GBK 16
#define A_BLK_STRIDE 132
#define B_BLK_STRIDE 68
#define A_STAGE_FLTS (16*A_BLK_STRIDE)
#define B_STAGE_FLTS (32*B_BLK_STRIDE)

__device__ __forceinline__ unsigned f2tf32(float f) {
    unsigned r;
    asm("cvt.rna.tf32.f32 %0, %1;" : "=r"(r) : "f"(f));
    return r;
}
__device__ __forceinline__ float f2tf32f(float f) { return __uint_as_float(f2tf32(f)); }

__device__ __forceinline__ float4 silu4mul(float4 gte, float4 yy) {
    float4 r;
    r.x = gte.x / (1.0f + expf(-gte.x)) * yy.x;
    r.y = gte.y / (1.0f + expf(-gte.y)) * yy.y;
    r.z = gte.z / (1.0f + expf(-gte.z)) * yy.z;
    r.w = gte.w / (1.0f + expf(-gte.w)) * yy.w;
    return r;
}

__device__ __forceinline__ void mma_tf32(float& c0, float& c1, float& c2, float& c3,
                                         unsigned a0, unsigned a1, unsigned a2, unsigned a3,
                                         unsigned b0, unsigned b1) {
    asm volatile(
        "mma.sync.aligned.m16n8k8.row.col.f32.tf32.tf32.f32 "
        "{%0,%1,%2,%3}, {%4,%5,%6,%7}, {%8,%9}, {%0,%1,%2,%3};"
        : "+f"(c0), "+f"(c1), "+f"(c2), "+f"(c3)
        : "r"(a0), "r"(a1), "r"(a2), "r"(a3), "r"(b0), "r"(b1));
}

template<int FUSE_SWIGLU>
__device__ __forceinline__ void mma_gemm_body(
    const float* __restrict__ A, const float* __restrict__ B,
    const float* __restrict__ addsrc, float* __restrict__ C,
    int N, int Kd, int lda, int bm, int bn) {
    __shared__ float As[2][A_STAGE_FLTS];
    __shared__ float Bs[2][B_STAGE_FLTS];

    int tid = threadIdx.x;
    int lane = tid & 31;
    int w    = tid >> 5;
    int lq = lane >> 2;
    int lr = lane & 3;
    int wm = w >> 2;
    int wn = w & 3;

    // A staging: tid = [mt(3)|lq(3)|ks(1)|jk(1)]
    int a_jk = tid & 1;
    int a_ks = (tid >> 1) & 1;
    int a_lq = (tid >> 2) & 7;
    int a_mt = tid >> 5;
    const float* Ag = A + (size_t)(bm + a_mt*16 + a_lq) * lda + a_ks*8 + a_jk*4;
    int a_sbase = (a_ks*8 + a_mt)*A_BLK_STRIDE + a_lq*16 + a_jk*2;

    // B staging
    int b_rb = tid >> 4;
    int b_nt = tid & 15;
    int b_ks = b_rb >> 3;
    int b_kr = b_rb & 7;
    int b_lr = b_kr & 3;
    int b_jk = b_kr >> 2;
    const float* Bg = B + (size_t)b_rb * N + bn + b_nt*8;
    int b_sbase = (b_ks*16 + b_nt)*B_BLK_STRIDE + b_lr*2 + b_jk;

    float acc[4][4][4];
    #pragma unroll
    for (int mi = 0; mi < 4; mi++)
        #pragma unroll
        for (int ni = 0; ni < 4; ni++)
            #pragma unroll
            for (int r = 0; r < 4; r++) acc[mi][ni][r] = 0.0f;

    int nch = Kd / GBK;

    float4 ar0, ar1, br0, br1;
    if (FUSE_SWIGLU) {
        ar0 = silu4mul(*(const float4*)(Ag), *(const float4*)(Ag + II));
        ar1 = silu4mul(*(const float4*)(Ag + (size_t)8*lda), *(const float4*)(Ag + (size_t)8*lda + II));
    } else {
        ar0 = *(const float4*)(Ag);
        ar1 = *(const float4*)(Ag + (size_t)8*lda);
    }
    br0 = *(const float4*)(Bg);
    br1 = *(const float4*)(Bg + 4);

    {
        float* as = As[0];
        float* bs = Bs[0];
        #pragma unroll
        for (int i = 0; i < 4; i++)
            *(float2*)(&as[a_sbase + i*4]) =
                make_float2(f2tf32f((&ar0.x)[i]), f2tf32f((&ar1.x)[i]));
        #pragma unroll
        for (int i = 0; i < 4; i++) bs[b_sbase + 8*i]      = f2tf32f((&br0.x)[i]);
        #pragma unroll
        for (int i = 0; i < 4; i++) bs[b_sbase + 8*(i+4)]  = f2tf32f((&br1.x)[i]);
    }
    __syncthreads();

    for (int ch = 0; ch < nch; ch++) {
        int s = ch & 1;
        if (ch + 1 < nch) {
            const float* Agn = Ag + (ch + 1) * GBK;
            const float* Bgn = Bg + (size_t)(ch + 1) * GBK * N;
            if (FUSE_SWIGLU) {
                ar0 = silu4mul(*(const float4*)(Agn), *(const float4*)(Agn + II));
                ar1 = silu4mul(*(const float4*)(Agn + (size_t)8*lda),
                               *(const float4*)(Agn + (size_t)8*lda + II));
            } else {
                ar0 = *(const float4*)(Agn);
                ar1 = *(const float4*)(Agn + (size_t)8*lda);
            }
            br0 = *(const float4*)(Bgn);
            br1 = *(const float4*)(Bgn + 4);
        }

        #pragma unroll
        for (int ksi = 0; ksi < 2; ksi++) {
            float4 afv[4];
            #pragma unroll
            for (int mi = 0; mi < 4; mi++)
                afv[mi] = *(const float4*)(&As[s][(ksi*8 + wm*4 + mi)*A_BLK_STRIDE + lane*4]);
            float2 bfv[4];
            #pragma unroll
            for (int ni = 0; ni < 4; ni++)
                bfv[ni] = *(const float2*)(&Bs[s][(ksi*16 + wn*4 + ni)*B_BLK_STRIDE + lane*2]);
            #pragma unroll
            for (int mi = 0; mi < 4; mi++)
                #pragma unroll
                for (int ni = 0; ni < 4; ni++)
                    mma_tf32(acc[mi][ni][0], acc[mi][ni][1], acc[mi][ni][2], acc[mi][ni][3],
                             __float_as_uint(afv[mi].x), __float_as_uint(afv[mi].y),
                             __float_as_uint(afv[mi].z), __float_as_uint(afv[mi].w),
                             __float_as_uint(bfv[ni].x), __float_as_uint(bfv[ni].y));
        }

        if (ch + 1 < nch) {
            float* as = As[s^1];
            float* bs = Bs[s^1];
            #pragma unroll
            for (int i = 0; i < 4; i++)
                *(float2*)(&as[a_sbase + i*4]) =
                    make_float2(f2tf32f((&ar0.x)[i]), f2tf32f((&ar1.x)[i]));
            #pragma unroll
            for (int i = 0; i < 4; i++) bs[b_sbase + 8*i]     = f2tf32f((&br0.x)[i]);
            #pragma unroll
            for (int i = 0; i < 4; i++) bs[b_sbase + 8*(i+4)] = f2tf32f((&br1.x)[i]);
            __syncthreads();
        }
    }

    #pragma unroll
    for (int mi = 0; mi < 4; mi++) {
        int r0 = bm + wm*64 + mi*16 + lq;
        #pragma unroll
        for (int ni = 0; ni < 4; ni++) {
            int col = bn + wn*32 + ni*8 + 2*lr;
            float2 v0 = make_float2(acc[mi][ni][0], acc[mi][ni][1]);
            float2 v1 = make_float2(acc[mi][ni][2], acc[mi][ni][3]);
            if (addsrc) {
                float2 s0 = *(const float2*)(addsrc + (size_t)r0 * N + col);
                float2 s1 = *(const float2*)(addsrc + (size_t)(r0+8) * N + col);
                v0.x += s0.x; v0.y += s0.y; v1.x += s1.x; v1.y += s1.y;
            }
            *(float2*)(C + (size_t)r0 * N + col) = v0;
            *(float2*)(C + (size_t)(r0+8) * N + col) = v1;
        }
    }
}

__global__ __launch_bounds__(256, 2) void mma_gemm_kernel(
    const float* __restrict__ A, const float* __restrict__ B,
    const float* __restrict__ addsrc, float* __restrict__ C,
    int N, int Kd) {
    mma_gemm_body<0>(A, B, addsrc, C, N, Kd, Kd, blockIdx.y * GBM, blockIdx.x * GBN);
}

__global__ __launch_bounds__(256, 2) void mma_gemm_qkv_kernel(
    const float* __restrict__ A,
    const float* __restrict__ B0, const float* __restrict__ B1, const float* __restrict__ B2,
    float* __restrict__ C0, float* __restrict__ C1, float* __restrict__ C2,
    int N, int Kd) {
    const float* B = (blockIdx.z == 0) ? B0 : ((blockIdx.z == 1) ? B1 : B2);
    float*       C = (blockIdx.z == 0) ? C0 : ((blockIdx.z == 1) ? C1 : C2);
    mma_gemm_body<0>(A, B, nullptr, C, N, Kd, Kd, blockIdx.y * GBM, blockIdx.x * GBN);
}

// Wd GEMM with swiglu fused into A staging: A = gy [M, 2*II], act = silu(gy[:, :II])*gy[:, II:]
__global__ __launch_bounds__(256, 2) void mma_gemm_swiglu_kernel(
    const float* __restrict__ gy, const float* __restrict__ B,
    const float* __restrict__ addsrc, float* __restrict__ C,
    int N) {
    mma_gemm_body<1>(gy, B, addsrc, C, N, II, 2*II, blockIdx.y * GBM, blockIdx.x * GBN);
}

// ---------------------------------------------------------------------------
// Fused causal depthwise conv1d (K=4) + SiLU + optional per-head L2 norm.
// One launch for q,k,v via blockIdx.y.
// ---------------------------------------------------------------------------
__global__ void conv_fused3_kernel(
    const float* __restrict__ xq, const float* __restrict__ wq, float* __restrict__ oq,
    const float* __restrict__ xk, const float* __restrict__ wk, float* __restrict__ ok,
    const float* __restrict__ xv, const float* __restrict__ wv, float* __restrict__ ov) {
    int which = blockIdx.y;
    const float* xin = (which == 0) ? xq : ((which == 1) ? xk : xv);
    const float* w   = (which == 0) ? wq : ((which == 1) ? wk : wv);
    float* out       = (which == 0) ? oq : ((which == 1) ? ok : ov);
    float scale = (which == 0) ? 0.125f : 1.0f;
    int do_l2   = (which != 2);

    int row = blockIdx.x;
    int t = row & (Tt - 1);
    int c4 = threadIdx.x * 4;
    size_t base = (size_t)row * Dd + c4;

    float4 x0 = *(const float4*)(xin + base);
    float4 x1 = (t >= 1) ? *(const float4*)(xin + base - Dd)   : make_float4(0,0,0,0);
    float4 x2 = (t >= 2) ? *(const float4*)(xin + base - 2*Dd) : make_float4(0,0,0,0);
    float4 x3 = (t >= 3) ? *(const float4*)(xin + base - 3*Dd) : make_float4(0,0,0,0);

    float y[4];
    #pragma unroll
    for (int j = 0; j < 4; j++) {
        float4 w4 = ((const float4*)w)[c4 + j];
        float a = (&x0.x)[j]*w4.w + (&x1.x)[j]*w4.z + (&x2.x)[j]*w4.y + (&x3.x)[j]*w4.x;
        y[j] = a / (1.0f + expf(-a));
    }

    if (do_l2) {
        float ss = y[0]*y[0] + y[1]*y[1] + y[2]*y[2] + y[3]*y[3];
        #pragma unroll
        for (int m = 8; m >= 1; m >>= 1) ss += __shfl_xor_sync(0xffffffffu, ss, m);
        float r = rsqrtf(ss + EPSf) * scale;
        #pragma unroll
        for (int j = 0; j < 4; j++) y[j] *= r;
    }
    *(float4*)(out + base) = make_float4(y[0], y[1], y[2], y[3]);
}

// ---------------------------------------------------------------------------
// Per-(b,t,h) RMSNorm over DV=64 with weight. In place.
// ---------------------------------------------------------------------------
__global__ void o_rmsnorm_kernel(float* __restrict__ o, const float* __restrict__ w) {
    int gidx = blockIdx.x * 8 + (threadIdx.x >> 5);
    int lane = threadIdx.x & 31;
    size_t base = (size_t)gidx * 64;
    float a = o[base + lane], b = o[base + 32 + lane];
    float ss = a*a + b*b;
    #pragma unroll
    for (int m = 16; m >= 1; m >>= 1) ss += __shfl_xor_sync(0xffffffffu, ss, m);
    float r = rsqrtf(ss * (1.0f/64.0f) + EPSf);
    o[base + lane]      = a * r * w[lane];
    o[base + 32 + lane] = b * r * w[lane + 32];
}

// ---------------------------------------------------------------------------
// beta / g projections
// ---------------------------------------------------------------------------
__global__ void betag_kernel(const float* __restrict__ h,
                             const float* __restrict__ Wb, const float* __restrict__ Wa,
                             const float* __restrict__ dt_bias, const float* __restrict__ A_log,
                             float* __restrict__ beta, float* __restrict__ g) {
    int row = blockIdx.x;
    __shared__ float hs[Dd];
    ((float4*)hs)[threadIdx.x] = ((const float4*)(h + (size_t)row * Dd))[threadIdx.x];
    __syncthreads();
    int hh = threadIdx.x >> 4;
    int l  = threadIdx.x & 15;
    float sb = 0.0f, sa = 0.0f;
    #pragma unroll 8
    for (int j = 0; j < 64; j++) {
        int d = l + 16*j;
        float hv = hs[d];
        sb += hv * Wb[d*Hh + hh];
        sa += hv * Wa[d*Hh + hh];
    }
    #pragma unroll
    for (int m = 8; m >= 1; m >>= 1) {
        sb += __shfl_xor_sync(0xffffffffu, sb, m);
        sa += __shfl_xor_sync(0xffffffffu, sa, m);
    }
    if (l == 0) {
        beta[row*Hh + hh] = 2.0f / (1.0f + expf(-sb));
        float xg = sa + dt_bias[hh];
        float sp = (xg > 15.0f) ? xg : log1pf(expf(xg));
        g[row*Hh + hh] = -expf(A_log[hh]) * sp;
    }
}

// ---------------------------------------------------------------------------
// Gated delta-rule scan, column-split. Grid (Hh, Bb, 2); each block owns 32
// of the 64 v-columns (columns evolve independently given shared k,q,beta,g).
// Thread: c_loc = tid>>3 (0..31), sub = tid&7 (rows sub*8..sub*8+7).
// ---------------------------------------------------------------------------
__device__ __forceinline__ float scan_load(const float* __restrict__ q,
                                           const float* __restrict__ k,
                                           const float* __restrict__ v,
                                           const float* __restrict__ beta,
                                           const float* __restrict__ g,
                                           int b, int h, int t, int tid) {
    size_t off = ((size_t)(b*Tt + t)) * 1024 + h * 64;
    if (tid < 64)  return k[off + tid];
    if (tid < 128) return q[off + tid - 64];
    if (tid < 192) return v[off + tid - 128];
    if (tid == 192) return beta[(size_t)(b*Tt + t)*Hh + h];
    return g[(size_t)(b*Tt + t)*Hh + h];
}

__global__ __launch_bounds__(256) void scan_kernel(
    const float* __restrict__ q, const float* __restrict__ k, const float* __restrict__ v,
    const float* __restrict__ beta, const float* __restrict__ g,
    float* __restrict__ o, float* __restrict__ state_out) {
    int h = blockIdx.x, b = blockIdx.y, half = blockIdx.z;
    int tid = threadIdx.x;
    int c_loc = tid >> 3;            // 0..31
    int sub   = tid & 7;             // 8 rows each
    int col   = half * 32 + c_loc;

    __shared__ __align__(16) float sh[2][200];

    float S[8];
    #pragma unroll
    for (int r = 0; r < 8; r++) S[r] = 0.0f;

    float rv = (tid < 194) ? scan_load(q, k, v, beta, g, b, h, 0, tid) : 0.0f;

    for (int t = 0; t < Tt; t++) {
        float* buf = sh[t & 1];
        if (tid < 194) buf[tid] = rv;
        __syncthreads();
        if (t + 1 < Tt && tid < 194)
            rv = scan_load(q, k, v, beta, g, b, h, t + 1, tid);

        float eg = expf(buf[193]);
        float bt = buf[192];

        const float4* kp4 = (const float4*)(buf + sub*8);
        const float4* qp4 = (const float4*)(buf + 64 + sub*8);
        float kr[8], qr[8];
        #pragma unroll
        for (int rr = 0; rr < 2; rr++) {
            float4 kv4 = kp4[rr];
            kr[rr*4+0] = kv4.x; kr[rr*4+1] = kv4.y; kr[rr*4+2] = kv4.z; kr[rr*4+3] = kv4.w;
            float4 qv4 = qp4[rr];
            qr[rr*4+0] = qv4.x; qr[rr*4+1] = qv4.y; qr[rr*4+2] = qv4.z; qr[rr*4+3] = qv4.w;
        }

        float kvp = 0.0f;
        #pragma unroll
        for (int r = 0; r < 8; r++) {
            S[r] *= eg;
            kvp += kr[r] * S[r];
        }
        kvp += __shfl_xor_sync(0xffffffffu, kvp, 1);
        kvp += __shfl_xor_sync(0xffffffffu, kvp, 2);
        kvp += __shfl_xor_sync(0xffffffffu, kvp, 4);

        float delta = (buf[128 + col] - kvp) * bt;

        float op = 0.0f;
        #pragma unroll
        for (int r = 0; r < 8; r++) {
            S[r] += kr[r] * delta;
            op += qr[r] * S[r];
        }
        op += __shfl_xor_sync(0xffffffffu, op, 1);
        op += __shfl_xor_sync(0xffffffffu, op, 2);
        op += __shfl_xor_sync(0xffffffffu, op, 4);
        if (sub == 0)
            o[((size_t)(b*Tt + t)*Hh + h) * DV + col] = op;
    }

    #pragma unroll
    for (int r = 0; r < 8; r++)
        state_out[((size_t)(b*Hh + h)*DK + sub*8 + r) * DV + col] = S[r];
}

// ---------------------------------------------------------------------------
// launch
// ---------------------------------------------------------------------------
extern "C" void kernel_launch(void* const* d_in, const int* in_sizes, int n_in,
                              void* d_out, int out_size) {
    const float* x           = (const float*)d_in[0];
    const float* attn_norm_w = (const float*)d_in[1];
    const float* Wq          = (const float*)d_in[2];
    const float* Wk          = (const float*)d_in[3];
    const float* Wv          = (const float*)d_in[4];
    const float* cq          = (const float*)d_in[5];
    const float* ck          = (const float*)d_in[6];
    const float* cv          = (const float*)d_in[7];
    const float* Wb          = (const float*)d_in[8];
    const float* Wa          = (const float*)d_in[9];
    const float* dt_bias     = (const float*)d_in[10];
    const float* A_log       = (const float*)d_in[11];
    const float* o_norm_w    = (const float*)d_in[12];
    const float* Wo          = (const float*)d_in[13];
    const float* mlp_norm_w  = (const float*)d_in[14];
    const float* Wg          = (const float*)d_in[15];
    const float* Wd          = (const float*)d_in[16];
    float* out = (float*)d_out;

    float *h, *qpre, *kpre, *vpre, *q, *k, *v, *beta, *gg, *o, *h2, *h3, *gy;
    cudaGetSymbolAddress((void**)&h,    g_h);
    cudaGetSymbolAddress((void**)&qpre, g_qpre);
    cudaGetSymbolAddress((void**)&kpre, g_kpre);
    cudaGetSymbolAddress((void**)&vpre, g_vpre);
    cudaGetSymbolAddress((void**)&q,    g_q);
    cudaGetSymbolAddress((void**)&k,    g_k);
    cudaGetSymbolAddress((void**)&v,    g_v);
    cudaGetSymbolAddress((void**)&beta, g_beta);
    cudaGetSymbolAddress((void**)&gg,   g_g);
    cudaGetSymbolAddress((void**)&o,    g_o);
    cudaGetSymbolAddress((void**)&h2,   g_h2);
    cudaGetSymbolAddress((void**)&h3,   g_h3);
    cudaGetSymbolAddress((void**)&gy,   g_gy);

    // 1. h = rmsnorm(x)
    rmsnorm_kernel<<<ROWS, 256>>>(x, attn_norm_w, h);

    // 2. q/k/v projections (one batched launch)
    dim3 gqkv(Dd/GBN, ROWS/GBM, 3);
    mma_gemm_qkv_kernel<<<gqkv, 256>>>(h, Wq, Wk, Wv, qpre, kpre, vpre, Dd, Dd);

    // 3. conv + silu (+ fused l2norm for q,k), one launch
    conv_fused3_kernel<<<dim3(ROWS, 3), 256>>>(qpre, cq, q, kpre, ck, k, vpre, cv, v);

    // 4. beta / g
    betag_kernel<<<ROWS, 256>>>(h, Wb, Wa, dt_bias, A_log, beta, gg);

    // 5. delta-rule scan (column-split x2; writes o and final state)
    scan_kernel<<<dim3(Hh, Bb, 2), 256>>>(q, k, v, beta, gg, o, out + (size_t)ROWS*Dd);

    // 6. per-head output RMSNorm
    o_rmsnorm_kernel<<<(ROWS*Hh)/8, 256>>>(o, o_norm_w);

    // 7. attn projection + residual
    dim3 g1024(Dd/GBN, ROWS/GBM);
    mma_gemm_kernel<<<g1024, 256>>>(o, Wo, x, h2, Dd, Dd);

    // 8. MLP
    rmsnorm_kernel<<<ROWS, 256>>>(h2, mlp_norm_w, h3);
    dim3 gwg((2*II)/GBN, ROWS/GBM);
    mma_gemm_kernel<<<gwg, 256>>>(h3, Wg, nullptr, gy, 2*II, Dd);
    // Wd with swiglu fused into the A-staging path
    mma_gemm_swiglu_kernel<<<g1024, 256>>>(gy, Wd, h2, out, Dd);
}

// round 8
// speedup vs baseline: 1.0971x; 1.0971x over previous
#include <cuda_runtime.h>
#include <math.h>

// ---------------------------------------------------------------------------
// Problem constants
// ---------------------------------------------------------------------------
#define Bb   4
#define Tt   1024
#define Dd   1024
#define Hh   16
#define DK   64
#define DV   64
#define II   2816
#define EPSf 1e-6f
#define ROWS (Bb*Tt)              // 4096

// ---------------------------------------------------------------------------
// Scratch (static device memory; no allocations allowed)
// ---------------------------------------------------------------------------
__device__ float g_h   [ROWS*Dd];      // rmsnorm(x)
__device__ float g_qpre[ROWS*Dd];
__device__ float g_kpre[ROWS*Dd];
__device__ float g_vpre[ROWS*Dd];
__device__ float g_q   [ROWS*Dd];
__device__ float g_k   [ROWS*Dd];
__device__ float g_v   [ROWS*Dd];
__device__ float g_beta[ROWS*Hh];
__device__ float g_g   [ROWS*Hh];
__device__ float g_o   [ROWS*Dd];      // attn output per head
__device__ float g_h2  [ROWS*Dd];      // x + attn_out
__device__ float g_h3  [ROWS*Dd];      // rmsnorm(h2)
__device__ float g_gy  [ROWS*2*II];    // h3 @ Wg
__device__ float g_act [ROWS*II];      // silu(gate)*y

// ---------------------------------------------------------------------------
// RMSNorm over D=1024, one block (256 thr) per row
// ---------------------------------------------------------------------------
__global__ void rmsnorm_kernel(const float* __restrict__ x, const float* __restrict__ w,
                               float* __restrict__ out) {
    int row = blockIdx.x;
    const float4* xr = (const float4*)(x + (size_t)row * Dd);
    float4 v = xr[threadIdx.x];
    float ss = v.x*v.x + v.y*v.y + v.z*v.z + v.w*v.w;
    #pragma unroll
    for (int m = 16; m >= 1; m >>= 1) ss += __shfl_xor_sync(0xffffffffu, ss, m);
    __shared__ float wsum[8];
    if ((threadIdx.x & 31) == 0) wsum[threadIdx.x >> 5] = ss;
    __syncthreads();
    float tot = wsum[0]+wsum[1]+wsum[2]+wsum[3]+wsum[4]+wsum[5]+wsum[6]+wsum[7];
    float r = rsqrtf(tot * (1.0f/Dd) + EPSf);
    float4 wv = ((const float4*)w)[threadIdx.x];
    float4 o;
    o.x = v.x*r*wv.x; o.y = v.y*r*wv.y; o.z = v.z*r*wv.z; o.w = v.w*r*wv.w;
    ((float4*)(out + (size_t)row * Dd))[threadIdx.x] = o;
}

// ---------------------------------------------------------------------------
// TF32 tensor-core GEMM: C[M,N] = A[M,K] @ B[K,N] (+addsrc)
// BM=128 BN=128 BK=16, 256 threads (8 warps, 2x4), warp tile 64x32,
// mma.sync.m16n8k8.tf32, double-buffered static smem (34.3KB -> 2 CTAs/SM).
// Fragment-permuted smem: A fragment = 1 LDS.128, B fragment = 1 LDS.64.
// ---------------------------------------------------------------------------
#define GBM 128
#define GBN 128
#define GBK 16
#define A_BLK_STRIDE 132
#define B_BLK_STRIDE 68
#define A_STAGE_FLTS (16*A_BLK_STRIDE)
#define B_STAGE_FLTS (32*B_BLK_STRIDE)

__device__ __forceinline__ unsigned f2tf32(float f) {
    unsigned r;
    asm("cvt.rna.tf32.f32 %0, %1;" : "=r"(r) : "f"(f));
    return r;
}
__device__ __forceinline__ float f2tf32f(float f) { return __uint_as_float(f2tf32(f)); }

__device__ __forceinline__ void mma_tf32(float& c0, float& c1, float& c2, float& c3,
                                         unsigned a0, unsigned a1, unsigned a2, unsigned a3,
                                         unsigned b0, unsigned b1) {
    asm volatile(
        "mma.sync.aligned.m16n8k8.row.col.f32.tf32.tf32.f32 "
        "{%0,%1,%2,%3}, {%4,%5,%6,%7}, {%8,%9}, {%0,%1,%2,%3};"
        : "+f"(c0), "+f"(c1), "+f"(c2), "+f"(c3)
        : "r"(a0), "r"(a1), "r"(a2), "r"(a3), "r"(b0), "r"(b1));
}

__device__ __forceinline__ void mma_gemm_body(
    const float* __restrict__ A, const float* __restrict__ B,
    const float* __restrict__ addsrc, float* __restrict__ C,
    int N, int Kd, int bm, int bn) {
    __shared__ float As[2][A_STAGE_FLTS];
    __shared__ float Bs[2][B_STAGE_FLTS];

    int tid = threadIdx.x;
    int lane = tid & 31;
    int w    = tid >> 5;
    int lq = lane >> 2;
    int lr = lane & 3;
    int wm = w >> 2;
    int wn = w & 3;

    // A staging: tid = [mt(3)|lq(3)|ks(1)|jk(1)]
    int a_jk = tid & 1;
    int a_ks = (tid >> 1) & 1;
    int a_lq = (tid >> 2) & 7;
    int a_mt = tid >> 5;
    const float* Ag = A + (size_t)(bm + a_mt*16 + a_lq) * Kd + a_ks*8 + a_jk*4;
    int a_sbase = (a_ks*8 + a_mt)*A_BLK_STRIDE + a_lq*16 + a_jk*2;

    // B staging
    int b_rb = tid >> 4;
    int b_nt = tid & 15;
    int b_ks = b_rb >> 3;
    int b_kr = b_rb & 7;
    int b_lr = b_kr & 3;
    int b_jk = b_kr >> 2;
    const float* Bg = B + (size_t)b_rb * N + bn + b_nt*8;
    int b_sbase = (b_ks*16 + b_nt)*B_BLK_STRIDE + b_lr*2 + b_jk;

    float acc[4][4][4];
    #pragma unroll
    for (int mi = 0; mi < 4; mi++)
        #pragma unroll
        for (int ni = 0; ni < 4; ni++)
            #pragma unroll
            for (int r = 0; r < 4; r++) acc[mi][ni][r] = 0.0f;

    int nch = Kd / GBK;

    float4 ar0, ar1, br0, br1;
    ar0 = *(const float4*)(Ag);
    ar1 = *(const float4*)(Ag + (size_t)8*Kd);
    br0 = *(const float4*)(Bg);
    br1 = *(const float4*)(Bg + 4);

    {
        float* as = As[0];
        float* bs = Bs[0];
        #pragma unroll
        for (int i = 0; i < 4; i++)
            *(float2*)(&as[a_sbase + i*4]) =
                make_float2(f2tf32f((&ar0.x)[i]), f2tf32f((&ar1.x)[i]));
        #pragma unroll
        for (int i = 0; i < 4; i++) bs[b_sbase + 8*i]      = f2tf32f((&br0.x)[i]);
        #pragma unroll
        for (int i = 0; i < 4; i++) bs[b_sbase + 8*(i+4)]  = f2tf32f((&br1.x)[i]);
    }
    __syncthreads();

    for (int ch = 0; ch < nch; ch++) {
        int s = ch & 1;
        if (ch + 1 < nch) {
            const float* Agn = Ag + (ch + 1) * GBK;
            const float* Bgn = Bg + (size_t)(ch + 1) * GBK * N;
            ar0 = *(const float4*)(Agn);
            ar1 = *(const float4*)(Agn + (size_t)8*Kd);
            br0 = *(const float4*)(Bgn);
            br1 = *(const float4*)(Bgn + 4);
        }

        #pragma unroll
        for (int ksi = 0; ksi < 2; ksi++) {
            float4 afv[4];
            #pragma unroll
            for (int mi = 0; mi < 4; mi++)
                afv[mi] = *(const float4*)(&As[s][(ksi*8 + wm*4 + mi)*A_BLK_STRIDE + lane*4]);
            float2 bfv[4];
            #pragma unroll
            for (int ni = 0; ni < 4; ni++)
                bfv[ni] = *(const float2*)(&Bs[s][(ksi*16 + wn*4 + ni)*B_BLK_STRIDE + lane*2]);
            #pragma unroll
            for (int mi = 0; mi < 4; mi++)
                #pragma unroll
                for (int ni = 0; ni < 4; ni++)
                    mma_tf32(acc[mi][ni][0], acc[mi][ni][1], acc[mi][ni][2], acc[mi][ni][3],
                             __float_as_uint(afv[mi].x), __float_as_uint(afv[mi].y),
                             __float_as_uint(afv[mi].z), __float_as_uint(afv[mi].w),
                             __float_as_uint(bfv[ni].x), __float_as_uint(bfv[ni].y));
        }

        if (ch + 1 < nch) {
            float* as = As[s^1];
            float* bs = Bs[s^1];
            #pragma unroll
            for (int i = 0; i < 4; i++)
                *(float2*)(&as[a_sbase + i*4]) =
                    make_float2(f2tf32f((&ar0.x)[i]), f2tf32f((&ar1.x)[i]));
            #pragma unroll
            for (int i = 0; i < 4; i++) bs[b_sbase + 8*i]     = f2tf32f((&br0.x)[i]);
            #pragma unroll
            for (int i = 0; i < 4; i++) bs[b_sbase + 8*(i+4)] = f2tf32f((&br1.x)[i]);
            __syncthreads();
        }
    }

    #pragma unroll
    for (int mi = 0; mi < 4; mi++) {
        int r0 = bm + wm*64 + mi*16 + lq;
        #pragma unroll
        for (int ni = 0; ni < 4; ni++) {
            int col = bn + wn*32 + ni*8 + 2*lr;
            float2 v0 = make_float2(acc[mi][ni][0], acc[mi][ni][1]);
            float2 v1 = make_float2(acc[mi][ni][2], acc[mi][ni][3]);
            if (addsrc) {
                float2 s0 = *(const float2*)(addsrc + (size_t)r0 * N + col);
                float2 s1 = *(const float2*)(addsrc + (size_t)(r0+8) * N + col);
                v0.x += s0.x; v0.y += s0.y; v1.x += s1.x; v1.y += s1.y;
            }
            *(float2*)(C + (size_t)r0 * N + col) = v0;
            *(float2*)(C + (size_t)(r0+8) * N + col) = v1;
        }
    }
}

__global__ __launch_bounds__(256, 2) void mma_gemm_kernel(
    const float* __restrict__ A, const float* __restrict__ B,
    const float* __restrict__ addsrc, float* __restrict__ C,
    int N, int Kd) {
    mma_gemm_body(A, B, addsrc, C, N, Kd, blockIdx.y * GBM, blockIdx.x * GBN);
}

__global__ __launch_bounds__(256, 2) void mma_gemm_qkv_kernel(
    const float* __restrict__ A,
    const float* __restrict__ B0, const float* __restrict__ B1, const float* __restrict__ B2,
    float* __restrict__ C0, float* __restrict__ C1, float* __restrict__ C2,
    int N, int Kd) {
    const float* B = (blockIdx.z == 0) ? B0 : ((blockIdx.z == 1) ? B1 : B2);
    float*       C = (blockIdx.z == 0) ? C0 : ((blockIdx.z == 1) ? C1 : C2);
    mma_gemm_body(A, B, nullptr, C, N, Kd, blockIdx.y * GBM, blockIdx.x * GBN);
}

// ---------------------------------------------------------------------------
// Fused causal depthwise conv1d (K=4) + SiLU + optional per-head L2 norm.
// One launch for q,k,v via blockIdx.y.
// ---------------------------------------------------------------------------
__global__ void conv_fused3_kernel(
    const float* __restrict__ xq, const float* __restrict__ wq, float* __restrict__ oq,
    const float* __restrict__ xk, const float* __restrict__ wk, float* __restrict__ ok,
    const float* __restrict__ xv, const float* __restrict__ wv, float* __restrict__ ov) {
    int which = blockIdx.y;
    const float* xin = (which == 0) ? xq : ((which == 1) ? xk : xv);
    const float* w   = (which == 0) ? wq : ((which == 1) ? wk : wv);
    float* out       = (which == 0) ? oq : ((which == 1) ? ok : ov);
    float scale = (which == 0) ? 0.125f : 1.0f;
    int do_l2   = (which != 2);

    int row = blockIdx.x;
    int t = row & (Tt - 1);
    int c4 = threadIdx.x * 4;
    size_t base = (size_t)row * Dd + c4;

    float4 x0 = *(const float4*)(xin + base);
    float4 x1 = (t >= 1) ? *(const float4*)(xin + base - Dd)   : make_float4(0,0,0,0);
    float4 x2 = (t >= 2) ? *(const float4*)(xin + base - 2*Dd) : make_float4(0,0,0,0);
    float4 x3 = (t >= 3) ? *(const float4*)(xin + base - 3*Dd) : make_float4(0,0,0,0);

    float y[4];
    #pragma unroll
    for (int j = 0; j < 4; j++) {
        float4 w4 = ((const float4*)w)[c4 + j];
        float a = (&x0.x)[j]*w4.w + (&x1.x)[j]*w4.z + (&x2.x)[j]*w4.y + (&x3.x)[j]*w4.x;
        y[j] = a / (1.0f + expf(-a));
    }

    if (do_l2) {
        float ss = y[0]*y[0] + y[1]*y[1] + y[2]*y[2] + y[3]*y[3];
        #pragma unroll
        for (int m = 8; m >= 1; m >>= 1) ss += __shfl_xor_sync(0xffffffffu, ss, m);
        float r = rsqrtf(ss + EPSf) * scale;
        #pragma unroll
        for (int j = 0; j < 4; j++) y[j] *= r;
    }
    *(float4*)(out + base) = make_float4(y[0], y[1], y[2], y[3]);
}

// ---------------------------------------------------------------------------
// Per-(b,t,h) RMSNorm over DV=64 with weight. In place.
// ---------------------------------------------------------------------------
__global__ void o_rmsnorm_kernel(float* __restrict__ o, const float* __restrict__ w) {
    int gidx = blockIdx.x * 8 + (threadIdx.x >> 5);
    int lane = threadIdx.x & 31;
    size_t base = (size_t)gidx * 64;
    float a = o[base + lane], b = o[base + 32 + lane];
    float ss = a*a + b*b;
    #pragma unroll
    for (int m = 16; m >= 1; m >>= 1) ss += __shfl_xor_sync(0xffffffffu, ss, m);
    float r = rsqrtf(ss * (1.0f/64.0f) + EPSf);
    o[base + lane]      = a * r * w[lane];
    o[base + 32 + lane] = b * r * w[lane + 32];
}

// ---------------------------------------------------------------------------
// beta / g projections: 128 blocks x 32 rows. Wb/Wa staged ONCE per block in
// dynamic smem (kills the 512MB of repeated L2 reads). Thread (grp,hh) with
// d = j*16 + grp  -> conflict-free LDS; h row prefetched into regs.
// ---------------------------------------------------------------------------
#define BETAG_BLOCKS 128
#define BETAG_RPB (ROWS/BETAG_BLOCKS)   // 32
#define BETAG_SMEM_FLTS (Dd*Hh*2 + Dd + 512)
#define BETAG_SMEM_BYTES (BETAG_SMEM_FLTS*4)

__global__ __launch_bounds__(256) void betag_kernel(
    const float* __restrict__ h,
    const float* __restrict__ Wb, const float* __restrict__ Wa,
    const float* __restrict__ dt_bias, const float* __restrict__ A_log,
    float* __restrict__ beta, float* __restrict__ g) {
    extern __shared__ float bsm[];
    float* wbs  = bsm;                 // [1024*16]
    float* was  = bsm + Dd*Hh;         // [1024*16]
    float* hrow = bsm + 2*Dd*Hh;       // [1024]
    float* red  = hrow + Dd;           // [2*256]

    int tid = threadIdx.x;
    // stage Wb/Wa (16384 floats each -> 4096 float4 each)
    for (int i = tid; i < 4096; i += 256) {
        ((float4*)wbs)[i] = ((const float4*)Wb)[i];
        ((float4*)was)[i] = ((const float4*)Wa)[i];
    }

    int hh  = tid & 15;
    int grp = tid >> 4;                // handles d = j*16 + grp
    int row0 = blockIdx.x * BETAG_RPB;

    float4 hv = ((const float4*)(h + (size_t)row0 * Dd))[tid];
    __syncthreads();

    for (int r = 0; r < BETAG_RPB; r++) {
        int row = row0 + r;
        ((float4*)hrow)[tid] = hv;
        __syncthreads();
        if (r + 1 < BETAG_RPB)
            hv = ((const float4*)(h + (size_t)(row + 1) * Dd))[tid];

        float sb = 0.0f, sa = 0.0f;
        #pragma unroll 8
        for (int j = 0; j < 64; j++) {
            int d = j*16 + grp;
            float hvv = hrow[d];
            sb += hvv * wbs[d*Hh + hh];
            sa += hvv * was[d*Hh + hh];
        }
        red[grp*16 + hh]       = sb;
        red[256 + grp*16 + hh] = sa;
        __syncthreads();

        if (tid < 32) {
            int hh2 = tid & 15, which = tid >> 4;
            const float* rp = red + which*256 + hh2;
            float s = 0.0f;
            #pragma unroll
            for (int gg2 = 0; gg2 < 16; gg2++) s += rp[gg2*16];
            if (which == 0) {
                beta[row*Hh + hh2] = 2.0f / (1.0f + expf(-s));
            } else {
                float xg = s + dt_bias[hh2];
                float sp = (xg > 15.0f) ? xg : log1pf(expf(xg));
                g[row*Hh + hh2] = -expf(A_log[hh2]) * sp;
            }
        }
        __syncthreads();
    }
}

// ---------------------------------------------------------------------------
// Gated delta-rule scan with register prefetch. One block per (b,h).
// (R5 version: 16 rows/thread, single block per chain.)
// ---------------------------------------------------------------------------
__device__ __forceinline__ float scan_load(const float* __restrict__ q,
                                           const float* __restrict__ k,
                                           const float* __restrict__ v,
                                           const float* __restrict__ beta,
                                           const float* __restrict__ g,
                                           int b, int h, int t, int tid) {
    size_t off = ((size_t)(b*Tt + t)) * 1024 + h * 64;
    if (tid < 64)  return k[off + tid];
    if (tid < 128) return q[off + tid - 64];
    if (tid < 192) return v[off + tid - 128];
    if (tid == 192) return beta[(size_t)(b*Tt + t)*Hh + h];
    return g[(size_t)(b*Tt + t)*Hh + h];
}

__global__ __launch_bounds__(256) void scan_kernel(
    const float* __restrict__ q, const float* __restrict__ k, const float* __restrict__ v,
    const float* __restrict__ beta, const float* __restrict__ g,
    float* __restrict__ o, float* __restrict__ state_out) {
    int h = blockIdx.x, b = blockIdx.y;
    int tid = threadIdx.x;
    int c   = tid >> 2;
    int sub = tid & 3;

    __shared__ __align__(16) float sh[2][200];

    float S[16];
    #pragma unroll
    for (int r = 0; r < 16; r++) S[r] = 0.0f;

    float rv = (tid < 194) ? scan_load(q, k, v, beta, g, b, h, 0, tid) : 0.0f;

    for (int t = 0; t < Tt; t++) {
        float* buf = sh[t & 1];
        if (tid < 194) buf[tid] = rv;
        __syncthreads();
        if (t + 1 < Tt && tid < 194)
            rv = scan_load(q, k, v, beta, g, b, h, t + 1, tid);

        float eg = expf(buf[193]);
        float bt = buf[192];

        const float4* kp4 = (const float4*)(buf + sub*16);
        const float4* qp4 = (const float4*)(buf + 64 + sub*16);
        float kr[16], qr[16];
        #pragma unroll
        for (int rr = 0; rr < 4; rr++) {
            float4 kv4 = kp4[rr];
            kr[rr*4+0] = kv4.x; kr[rr*4+1] = kv4.y; kr[rr*4+2] = kv4.z; kr[rr*4+3] = kv4.w;
            float4 qv4 = qp4[rr];
            qr[rr*4+0] = qv4.x; qr[rr*4+1] = qv4.y; qr[rr*4+2] = qv4.z; qr[rr*4+3] = qv4.w;
        }

        float kvp = 0.0f;
        #pragma unroll
        for (int r = 0; r < 16; r++) {
            S[r] *= eg;
            kvp += kr[r] * S[r];
        }
        kvp += __shfl_xor_sync(0xffffffffu, kvp, 1);
        kvp += __shfl_xor_sync(0xffffffffu, kvp, 2);

        float delta = (buf[128 + c] - kvp) * bt;

        float op = 0.0f;
        #pragma unroll
        for (int r = 0; r < 16; r++) {
            S[r] += kr[r] * delta;
            op += qr[r] * S[r];
        }
        op += __shfl_xor_sync(0xffffffffu, op, 1);
        op += __shfl_xor_sync(0xffffffffu, op, 2);
        if (sub == 0)
            o[((size_t)(b*Tt + t)*Hh + h) * DV + c] = op;
    }

    #pragma unroll
    for (int r = 0; r < 16; r++)
        state_out[((size_t)(b*Hh + h)*DK + sub*16 + r) * DV + c] = S[r];
}

// ---------------------------------------------------------------------------
// SwiGLU: act = silu(gy[:, :I]) * gy[:, I:]
// ---------------------------------------------------------------------------
__global__ void swiglu_kernel(const float* __restrict__ gy, float* __restrict__ act) {
    int idx = blockIdx.x * blockDim.x + threadIdx.x;
    int row = idx / II;
    int i   = idx - row * II;
    float gate = gy[(size_t)row * (2*II) + i];
    float y    = gy[(size_t)row * (2*II) + II + i];
    act[idx] = gate / (1.0f + expf(-gate)) * y;
}

// ---------------------------------------------------------------------------
// launch
// ---------------------------------------------------------------------------
extern "C" void kernel_launch(void* const* d_in, const int* in_sizes, int n_in,
                              void* d_out, int out_size) {
    const float* x           = (const float*)d_in[0];
    const float* attn_norm_w = (const float*)d_in[1];
    const float* Wq          = (const float*)d_in[2];
    const float* Wk          = (const float*)d_in[3];
    const float* Wv          = (const float*)d_in[4];
    const float* cq          = (const float*)d_in[5];
    const float* ck          = (const float*)d_in[6];
    const float* cv          = (const float*)d_in[7];
    const float* Wb          = (const float*)d_in[8];
    const float* Wa          = (const float*)d_in[9];
    const float* dt_bias     = (const float*)d_in[10];
    const float* A_log       = (const float*)d_in[11];
    const float* o_norm_w    = (const float*)d_in[12];
    const float* Wo          = (const float*)d_in[13];
    const float* mlp_norm_w  = (const float*)d_in[14];
    const float* Wg          = (const float*)d_in[15];
    const float* Wd          = (const float*)d_in[16];
    float* out = (float*)d_out;

    float *h, *qpre, *kpre, *vpre, *q, *k, *v, *beta, *gg, *o, *h2, *h3, *gy, *act;
    cudaGetSymbolAddress((void**)&h,    g_h);
    cudaGetSymbolAddress((void**)&qpre, g_qpre);
    cudaGetSymbolAddress((void**)&kpre, g_kpre);
    cudaGetSymbolAddress((void**)&vpre, g_vpre);
    cudaGetSymbolAddress((void**)&q,    g_q);
    cudaGetSymbolAddress((void**)&k,    g_k);
    cudaGetSymbolAddress((void**)&v,    g_v);
    cudaGetSymbolAddress((void**)&beta, g_beta);
    cudaGetSymbolAddress((void**)&gg,   g_g);
    cudaGetSymbolAddress((void**)&o,    g_o);
    cudaGetSymbolAddress((void**)&h2,   g_h2);
    cudaGetSymbolAddress((void**)&h3,   g_h3);
    cudaGetSymbolAddress((void**)&gy,   g_gy);
    cudaGetSymbolAddress((void**)&act,  g_act);

    cudaFuncSetAttribute(betag_kernel,
                         cudaFuncAttributeMaxDynamicSharedMemorySize, BETAG_SMEM_BYTES);

    // 1. h = rmsnorm(x)
    rmsnorm_kernel<<<ROWS, 256>>>(x, attn_norm_w, h);

    // 2. q/k/v projections (one batched launch)
    dim3 gqkv(Dd/GBN, ROWS/GBM, 3);
    mma_gemm_qkv_kernel<<<gqkv, 256>>>(h, Wq, Wk, Wv, qpre, kpre, vpre, Dd, Dd);

    // 3. conv + silu (+ fused l2norm for q,k), one launch
    conv_fused3_kernel<<<dim3(ROWS, 3), 256>>>(qpre, cq, q, kpre, ck, k, vpre, cv, v);

    // 4. beta / g (smem-staged weights)
    betag_kernel<<<BETAG_BLOCKS, 256, BETAG_SMEM_BYTES>>>(h, Wb, Wa, dt_bias, A_log, beta, gg);

    // 5. delta-rule scan (writes o and final state)
    scan_kernel<<<dim3(Hh, Bb), 256>>>(q, k, v, beta, gg, o, out + (size_t)ROWS*Dd);

    // 6. per-head output RMSNorm
    o_rmsnorm_kernel<<<(ROWS*Hh)/8, 256>>>(o, o_norm_w);

    // 7. attn projection + residual
    dim3 g1024(Dd/GBN, ROWS/GBM);
    mma_gemm_kernel<<<g1024, 256>>>(o, Wo, x, h2, Dd, Dd);

    // 8. MLP
    rmsnorm_kernel<<<ROWS, 256>>>(h2, mlp_norm_w, h3);
    dim3 gwg((2*II)/GBN, ROWS/GBM);
    mma_gemm_kernel<<<gwg, 256>>>(h3, Wg, nullptr, gy, 2*II, Dd);
    swiglu_kernel<<<(ROWS*II)/256, 256>>>(gy, act);
    mma_gemm_kernel<<<g1024, 256>>>(act, Wd, h2, out, Dd, II);
}

// round 10
// speedup vs baseline: 1.1267x; 1.0269x over previous
#include <cuda_runtime.h>
#include <math.h>

// ---------------------------------------------------------------------------
// Problem constants
// ---------------------------------------------------------------------------
#define Bb   4
#define Tt   1024
#define Dd   1024
#define Hh   16
#define DK   64
#define DV   64
#define II   2816
#define EPSf 1e-6f
#define ROWS (Bb*Tt)              // 4096

// ---------------------------------------------------------------------------
// Scratch (static device memory; no allocations allowed)
// ---------------------------------------------------------------------------
__device__ float g_h   [ROWS*Dd];      // rmsnorm(x)
__device__ float g_qpre[ROWS*Dd];
__device__ float g_kpre[ROWS*Dd];
__device__ float g_vpre[ROWS*Dd];
__device__ float g_q   [ROWS*Dd];
__device__ float g_k   [ROWS*Dd];
__device__ float g_v   [ROWS*Dd];
__device__ float g_beta[ROWS*Hh];
__device__ float g_g   [ROWS*Hh];
__device__ float g_o   [ROWS*Dd];      // attn output per head
__device__ float g_h2  [ROWS*Dd];      // x + attn_out
__device__ float g_h3  [ROWS*Dd];      // rmsnorm(h2)
__device__ float g_gy  [ROWS*2*II];    // h3 @ Wg
__device__ float g_act [ROWS*II];      // silu(gate)*y

// ---------------------------------------------------------------------------
// RMSNorm over D=1024, one block (256 thr) per row
// ---------------------------------------------------------------------------
__global__ void rmsnorm_kernel(const float* __restrict__ x, const float* __restrict__ w,
                               float* __restrict__ out) {
    int row = blockIdx.x;
    const float4* xr = (const float4*)(x + (size_t)row * Dd);
    float4 v = xr[threadIdx.x];
    float ss = v.x*v.x + v.y*v.y + v.z*v.z + v.w*v.w;
    #pragma unroll
    for (int m = 16; m >= 1; m >>= 1) ss += __shfl_xor_sync(0xffffffffu, ss, m);
    __shared__ float wsum[8];
    if ((threadIdx.x & 31) == 0) wsum[threadIdx.x >> 5] = ss;
    __syncthreads();
    float tot = wsum[0]+wsum[1]+wsum[2]+wsum[3]+wsum[4]+wsum[5]+wsum[6]+wsum[7];
    float r = rsqrtf(tot * (1.0f/Dd) + EPSf);
    float4 wv = ((const float4*)w)[threadIdx.x];
    float4 o;
    o.x = v.x*r*wv.x; o.y = v.y*r*wv.y; o.z = v.z*r*wv.z; o.w = v.w*r*wv.w;
    ((float4*)(out + (size_t)row * Dd))[threadIdx.x] = o;
}

// ---------------------------------------------------------------------------
// TF32 tensor-core GEMM: C[M,N] = A[M,K] @ B[K,N] (+addsrc)
// BM=128 BN=128 BK=16, 256 threads (8 warps, 2x4), warp tile 64x32,
// mma.sync.m16n8k8.tf32, double-buffered static smem (34.3KB -> 2 CTAs/SM).
// Fragment-permuted smem: A fragment = 1 LDS.128, B fragment = 1 LDS.64.
// ---------------------------------------------------------------------------
#define GBM 128
#define GBN 128
#define GBK 16
#define A_BLK_STRIDE 132
#define B_BLK_STRIDE 68
#define A_STAGE_FLTS (16*A_BLK_STRIDE)
#define B_STAGE_FLTS (32*B_BLK_STRIDE)

__device__ __forceinline__ unsigned f2tf32(float f) {
    unsigned r;
    asm("cvt.rna.tf32.f32 %0, %1;" : "=r"(r) : "f"(f));
    return r;
}
__device__ __forceinline__ float f2tf32f(float f) { return __uint_as_float(f2tf32(f)); }

__device__ __forceinline__ void mma_tf32(float& c0, float& c1, float& c2, float& c3,
                                         unsigned a0, unsigned a1, unsigned a2, unsigned a3,
                                         unsigned b0, unsigned b1) {
    asm volatile(
        "mma.sync.aligned.m16n8k8.row.col.f32.tf32.tf32.f32 "
        "{%0,%1,%2,%3}, {%4,%5,%6,%7}, {%8,%9}, {%0,%1,%2,%3};"
        : "+f"(c0), "+f"(c1), "+f"(c2), "+f"(c3)
        : "r"(a0), "r"(a1), "r"(a2), "r"(a3), "r"(b0), "r"(b1));
}

__device__ __forceinline__ void mma_gemm_body(
    const float* __restrict__ A, const float* __restrict__ B,
    const float* __restrict__ addsrc, float* __restrict__ C,
    int N, int Kd, int bm, int bn) {
    __shared__ float As[2][A_STAGE_FLTS];
    __shared__ float Bs[2][B_STAGE_FLTS];

    int tid = threadIdx.x;
    int lane = tid & 31;
    int w    = tid >> 5;
    int lq = lane >> 2;
    int lr = lane & 3;
    int wm = w >> 2;
    int wn = w & 3;

    int a_jk = tid & 1;
    int a_ks = (tid >> 1) & 1;
    int a_lq = (tid >> 2) & 7;
    int a_mt = tid >> 5;
    const float* Ag = A + (size_t)(bm + a_mt*16 + a_lq) * Kd + a_ks*8 + a_jk*4;
    int a_sbase = (a_ks*8 + a_mt)*A_BLK_STRIDE + a_lq*16 + a_jk*2;

    int b_rb = tid >> 4;
    int b_nt = tid & 15;
    int b_ks = b_rb >> 3;
    int b_kr = b_rb & 7;
    int b_lr = b_kr & 3;
    int b_jk = b_kr >> 2;
    const float* Bg = B + (size_t)b_rb * N + bn + b_nt*8;
    int b_sbase = (b_ks*16 + b_nt)*B_BLK_STRIDE + b_lr*2 + b_jk;

    float acc[4][4][4];
    #pragma unroll
    for (int mi = 0; mi < 4; mi++)
        #pragma unroll
        for (int ni = 0; ni < 4; ni++)
            #pragma unroll
            for (int r = 0; r < 4; r++) acc[mi][ni][r] = 0.0f;

    int nch = Kd / GBK;

    float4 ar0, ar1, br0, br1;
    ar0 = *(const float4*)(Ag);
    ar1 = *(const float4*)(Ag + (size_t)8*Kd);
    br0 = *(const float4*)(Bg);
    br1 = *(const float4*)(Bg + 4);

    {
        float* as = As[0];
        float* bs = Bs[0];
        #pragma unroll
        for (int i = 0; i < 4; i++)
            *(float2*)(&as[a_sbase + i*4]) =
                make_float2(f2tf32f((&ar0.x)[i]), f2tf32f((&ar1.x)[i]));
        #pragma unroll
        for (int i = 0; i < 4; i++) bs[b_sbase + 8*i]      = f2tf32f((&br0.x)[i]);
        #pragma unroll
        for (int i = 0; i < 4; i++) bs[b_sbase + 8*(i+4)]  = f2tf32f((&br1.x)[i]);
    }
    __syncthreads();

    for (int ch = 0; ch < nch; ch++) {
        int s = ch & 1;
        if (ch + 1 < nch) {
            const float* Agn = Ag + (ch + 1) * GBK;
            const float* Bgn = Bg + (size_t)(ch + 1) * GBK * N;
            ar0 = *(const float4*)(Agn);
            ar1 = *(const float4*)(Agn + (size_t)8*Kd);
            br0 = *(const float4*)(Bgn);
            br1 = *(const float4*)(Bgn + 4);
        }

        #pragma unroll
        for (int ksi = 0; ksi < 2; ksi++) {
            float4 afv[4];
            #pragma unroll
            for (int mi = 0; mi < 4; mi++)
                afv[mi] = *(const float4*)(&As[s][(ksi*8 + wm*4 + mi)*A_BLK_STRIDE + lane*4]);
            float2 bfv[4];
            #pragma unroll
            for (int ni = 0; ni < 4; ni++)
                bfv[ni] = *(const float2*)(&Bs[s][(ksi*16 + wn*4 + ni)*B_BLK_STRIDE + lane*2]);
            #pragma unroll
            for (int mi = 0; mi < 4; mi++)
                #pragma unroll
                for (int ni = 0; ni < 4; ni++)
                    mma_tf32(acc[mi][ni][0], acc[mi][ni][1], acc[mi][ni][2], acc[mi][ni][3],
                             __float_as_uint(afv[mi].x), __float_as_uint(afv[mi].y),
                             __float_as_uint(afv[mi].z), __float_as_uint(afv[mi].w),
                             __float_as_uint(bfv[ni].x), __float_as_uint(bfv[ni].y));
        }

        if (ch + 1 < nch) {
            float* as = As[s^1];
            float* bs = Bs[s^1];
            #pragma unroll
            for (int i = 0; i < 4; i++)
                *(float2*)(&as[a_sbase + i*4]) =
                    make_float2(f2tf32f((&ar0.x)[i]), f2tf32f((&ar1.x)[i]));
            #pragma unroll
            for (int i = 0; i < 4; i++) bs[b_sbase + 8*i]     = f2tf32f((&br0.x)[i]);
            #pragma unroll
            for (int i = 0; i < 4; i++) bs[b_sbase + 8*(i+4)] = f2tf32f((&br1.x)[i]);
            __syncthreads();
        }
    }

    #pragma unroll
    for (int mi = 0; mi < 4; mi++) {
        int r0 = bm + wm*64 + mi*16 + lq;
        #pragma unroll
        for (int ni = 0; ni < 4; ni++) {
            int col = bn + wn*32 + ni*8 + 2*lr;
            float2 v0 = make_float2(acc[mi][ni][0], acc[mi][ni][1]);
            float2 v1 = make_float2(acc[mi][ni][2], acc[mi][ni][3]);
            if (addsrc) {
                float2 s0 = *(const float2*)(addsrc + (size_t)r0 * N + col);
                float2 s1 = *(const float2*)(addsrc + (size_t)(r0+8) * N + col);
                v0.x += s0.x; v0.y += s0.y; v1.x += s1.x; v1.y += s1.y;
            }
            *(float2*)(C + (size_t)r0 * N + col) = v0;
            *(float2*)(C + (size_t)(r0+8) * N + col) = v1;
        }
    }
}

__global__ __launch_bounds__(256, 2) void mma_gemm_kernel(
    const float* __restrict__ A, const float* __restrict__ B,
    const float* __restrict__ addsrc, float* __restrict__ C,
    int N, int Kd) {
    mma_gemm_body(A, B, addsrc, C, N, Kd, blockIdx.y * GBM, blockIdx.x * GBN);
}

__global__ __launch_bounds__(256, 2) void mma_gemm_qkv_kernel(
    const float* __restrict__ A,
    const float* __restrict__ B0, const float* __restrict__ B1, const float* __restrict__ B2,
    float* __restrict__ C0, float* __restrict__ C1, float* __restrict__ C2,
    int N, int Kd) {
    const float* B = (blockIdx.z == 0) ? B0 : ((blockIdx.z == 1) ? B1 : B2);
    float*       C = (blockIdx.z == 0) ? C0 : ((blockIdx.z == 1) ? C1 : C2);
    mma_gemm_body(A, B, nullptr, C, N, Kd, blockIdx.y * GBM, blockIdx.x * GBN);
}

// ---------------------------------------------------------------------------
// Fused causal depthwise conv1d (K=4) + SiLU + optional per-head L2 norm.
// ---------------------------------------------------------------------------
__global__ void conv_fused3_kernel(
    const float* __restrict__ xq, const float* __restrict__ wq, float* __restrict__ oq,
    const float* __restrict__ xk, const float* __restrict__ wk, float* __restrict__ ok,
    const float* __restrict__ xv, const float* __restrict__ wv, float* __restrict__ ov) {
    int which = blockIdx.y;
    const float* xin = (which == 0) ? xq : ((which == 1) ? xk : xv);
    const float* w   = (which == 0) ? wq : ((which == 1) ? wk : wv);
    float* out       = (which == 0) ? oq : ((which == 1) ? ok : ov);
    float scale = (which == 0) ? 0.125f : 1.0f;
    int do_l2   = (which != 2);

    int row = blockIdx.x;
    int t = row & (Tt - 1);
    int c4 = threadIdx.x * 4;
    size_t base = (size_t)row * Dd + c4;

    float4 x0 = *(const float4*)(xin + base);
    float4 x1 = (t >= 1) ? *(const float4*)(xin + base - Dd)   : make_float4(0,0,0,0);
    float4 x2 = (t >= 2) ? *(const float4*)(xin + base - 2*Dd) : make_float4(0,0,0,0);
    float4 x3 = (t >= 3) ? *(const float4*)(xin + base - 3*Dd) : make_float4(0,0,0,0);

    float y[4];
    #pragma unroll
    for (int j = 0; j < 4; j++) {
        float4 w4 = ((const float4*)w)[c4 + j];
        float a = (&x0.x)[j]*w4.w + (&x1.x)[j]*w4.z + (&x2.x)[j]*w4.y + (&x3.x)[j]*w4.x;
        y[j] = a / (1.0f + expf(-a));
    }

    if (do_l2) {
        float ss = y[0]*y[0] + y[1]*y[1] + y[2]*y[2] + y[3]*y[3];
        #pragma unroll
        for (int m = 8; m >= 1; m >>= 1) ss += __shfl_xor_sync(0xffffffffu, ss, m);
        float r = rsqrtf(ss + EPSf) * scale;
        #pragma unroll
        for (int j = 0; j < 4; j++) y[j] *= r;
    }
    *(float4*)(out + base) = make_float4(y[0], y[1], y[2], y[3]);
}

// ---------------------------------------------------------------------------
// Per-(b,t,h) RMSNorm over DV=64 with weight. In place.
// ---------------------------------------------------------------------------
__global__ void o_rmsnorm_kernel(float* __restrict__ o, const float* __restrict__ w) {
    int gidx = blockIdx.x * 8 + (threadIdx.x >> 5);
    int lane = threadIdx.x & 31;
    size_t base = (size_t)gidx * 64;
    float a = o[base + lane], b = o[base + 32 + lane];
    float ss = a*a + b*b;
    #pragma unroll
    for (int m = 16; m >= 1; m >>= 1) ss += __shfl_xor_sync(0xffffffffu, ss, m);
    float r = rsqrtf(ss * (1.0f/64.0f) + EPSf);
    o[base + lane]      = a * r * w[lane];
    o[base + 32 + lane] = b * r * w[lane + 32];
}

// ---------------------------------------------------------------------------
// beta / g projections v3: 128 blocks x 32 rows (2 passes of 16).
// Weights staged once (128KB smem); 16 rows of h staged per pass (64KB);
// each thread carries 16 rows of accumulators in REGISTERS so each weight
// LDS pair feeds 32 FMAs (row-level ILP breaks the latency chain).
// ---------------------------------------------------------------------------
#define BETAG_BLOCKS 128
#define BETAG_RPB 32
#define BETAG_PASS 16
#define BETAG_SMEM_FLTS (2*Dd*Hh + BETAG_PASS*Dd)    // 32768 + 16384
#define BETAG_SMEM_BYTES (BETAG_SMEM_FLTS*4)          // 196608 B

__global__ __launch_bounds__(256) void betag_kernel(
    const float* __restrict__ h,
    const float* __restrict__ Wb, const float* __restrict__ Wa,
    const float* __restrict__ dt_bias, const float* __restrict__ A_log,
    float* __restrict__ beta, float* __restrict__ g) {
    extern __shared__ float bsm[];
    float* wbs = bsm;                  // [1024*16]
    float* was = bsm + Dd*Hh;          // [1024*16]
    float* hst = bsm + 2*Dd*Hh;        // [16*1024]; reused as reduction buffer

    int tid = threadIdx.x;
    int hh  = tid & 15;
    int grp = tid >> 4;
    int row0 = blockIdx.x * BETAG_RPB;

    // stage Wb/Wa: 32768 floats = 8192 float4
    for (int i = tid; i < 8192; i += 256) {
        float4 vb = ((const float4*)Wb)[i & 4095];
        if (i < 4096) ((float4*)wbs)[i] = vb;
        else          ((float4*)was)[i - 4096] = ((const float4*)Wa)[i - 4096];
    }

    for (int p = 0; p < 2; p++) {
        int prow0 = row0 + p * BETAG_PASS;
        __syncthreads();           // protect hst reuse (reduction of prev pass done)
        // stage 16 h rows: 4096 float4
        for (int i = tid; i < 4096; i += 256)
            ((float4*)hst)[i] = ((const float4*)(h + (size_t)prow0 * Dd))[i];
        __syncthreads();

        float sb[BETAG_PASS], sa[BETAG_PASS];
        #pragma unroll
        for (int r = 0; r < BETAG_PASS; r++) { sb[r] = 0.0f; sa[r] = 0.0f; }

        #pragma unroll 4
        for (int j = 0; j < 64; j++) {
            int d = j*16 + grp;
            float wb = wbs[d*Hh + hh];
            float wa = was[d*Hh + hh];
            #pragma unroll
            for (int r = 0; r < BETAG_PASS; r++) {
                float hv = hst[r*Dd + d];
                sb[r] += hv * wb;
                sa[r] += hv * wa;
            }
        }
        __syncthreads();           // hst reads done; reuse as reduction buffer

        // red layout: [r][0:256)=sb partials, [r][256:512)=sa partials
        #pragma unroll
        for (int r = 0; r < BETAG_PASS; r++) {
            hst[(r<<9) + (grp<<4) + hh]       = sb[r];
            hst[(r<<9) + 256 + (grp<<4) + hh] = sa[r];
        }
        __syncthreads();

        // 512 outputs (16 rows x 16 heads x 2 kinds); 2 per thread
        #pragma unroll
        for (int u = 0; u < 2; u++) {
            int idx = tid + u*256;             // [r(4b)|which(1b)|hh(4b)]
            int r2    = idx >> 5;
            int which = (idx >> 4) & 1;
            int hh2   = idx & 15;
            const float* rp = hst + (r2<<9) + which*256 + hh2;
            float s = 0.0f;
            #pragma unroll
            for (int gg2 = 0; gg2 < 16; gg2++) s += rp[gg2*16];
            int row = prow0 + r2;
            if (which == 0) {
                beta[row*Hh + hh2] = 2.0f / (1.0f + expf(-s));
            } else {
                float xg = s + dt_bias[hh2];
                float sp = (xg > 15.0f) ? xg : log1pf(expf(xg));
                g[row*Hh + hh2] = -expf(A_log[hh2]) * sp;
            }
        }
    }
}

// ---------------------------------------------------------------------------
// Gated delta-rule scan with register prefetch + split reduction chains.
// One block per (b,h); thread (c = tid>>2, sub = tid&3) owns 16 rows.
// ---------------------------------------------------------------------------
__device__ __forceinline__ float scan_load(const float* __restrict__ q,
                                           const float* __restrict__ k,
                                           const float* __restrict__ v,
                                           const float* __restrict__ beta,
                                           const float* __restrict__ g,
                                           int b, int h, int t, int tid) {
    size_t off = ((size_t)(b*Tt + t)) * 1024 + h * 64;
    if (tid < 64)  return k[off + tid];
    if (tid < 128) return q[off + tid - 64];
    if (tid < 192) return v[off + tid - 128];
    if (tid == 192) return beta[(size_t)(b*Tt + t)*Hh + h];
    return g[(size_t)(b*Tt + t)*Hh + h];
}

__global__ __launch_bounds__(256) void scan_kernel(
    const float* __restrict__ q, const float* __restrict__ k, const float* __restrict__ v,
    const float* __restrict__ beta, const float* __restrict__ g,
    float* __restrict__ o, float* __restrict__ state_out) {
    int h = blockIdx.x, b = blockIdx.y;
    int tid = threadIdx.x;
    int c   = tid >> 2;
    int sub = tid & 3;

    __shared__ __align__(16) float sh[2][200];

    float S[16];
    #pragma unroll
    for (int r = 0; r < 16; r++) S[r] = 0.0f;

    float rv = (tid < 194) ? scan_load(q, k, v, beta, g, b, h, 0, tid) : 0.0f;

    for (int t = 0; t < Tt; t++) {
        float* buf = sh[t & 1];
        if (tid < 194) buf[tid] = rv;
        __syncthreads();
        if (t + 1 < Tt && tid < 194)
            rv = scan_load(q, k, v, beta, g, b, h, t + 1, tid);

        float eg = expf(buf[193]);
        float bt = buf[192];

        const float4* kp4 = (const float4*)(buf + sub*16);
        const float4* qp4 = (const float4*)(buf + 64 + sub*16);
        float kr[16], qr[16];
        #pragma unroll
        for (int rr = 0; rr < 4; rr++) {
            float4 kv4 = kp4[rr];
            kr[rr*4+0] = kv4.x; kr[rr*4+1] = kv4.y; kr[rr*4+2] = kv4.z; kr[rr*4+3] = kv4.w;
            float4 qv4 = qp4[rr];
            qr[rr*4+0] = qv4.x; qr[rr*4+1] = qv4.y; qr[rr*4+2] = qv4.z; qr[rr*4+3] = qv4.w;
        }

        // 4 independent partial sums break the 16-deep FMA chain
        float k0 = 0.0f, k1 = 0.0f, k2 = 0.0f, k3 = 0.0f;
        #pragma unroll
        for (int r4 = 0; r4 < 4; r4++) {
            S[4*r4+0] *= eg; k0 += kr[4*r4+0] * S[4*r4+0];
            S[4*r4+1] *= eg; k1 += kr[4*r4+1] * S[4*r4+1];
            S[4*r4+2] *= eg; k2 += kr[4*r4+2] * S[4*r4+2];
            S[4*r4+3] *= eg; k3 += kr[4*r4+3] * S[4*r4+3];
        }
        float kvp = (k0 + k1) + (k2 + k3);
        kvp += __shfl_xor_sync(0xffffffffu, kvp, 1);
        kvp += __shfl_xor_sync(0xffffffffu, kvp, 2);

        float delta = (buf[128 + c] - kvp) * bt;

        float o0 = 0.0f, o1 = 0.0f, o2 = 0.0f, o3 = 0.0f;
        #pragma unroll
        for (int r4 = 0; r4 < 4; r4++) {
            S[4*r4+0] += kr[4*r4+0] * delta; o0 += qr[4*r4+0] * S[4*r4+0];
            S[4*r4+1] += kr[4*r4+1] * delta; o1 += qr[4*r4+1] * S[4*r4+1];
            S[4*r4+2] += kr[4*r4+2] * delta; o2 += qr[4*r4+2] * S[4*r4+2];
            S[4*r4+3] += kr[4*r4+3] * delta; o3 += qr[4*r4+3] * S[4*r4+3];
        }
        float op = (o0 + o1) + (o2 + o3);
        op += __shfl_xor_sync(0xffffffffu, op, 1);
        op += __shfl_xor_sync(0xffffffffu, op, 2);
        if (sub == 0)
            o[((size_t)(b*Tt + t)*Hh + h) * DV + c] = op;
    }

    #pragma unroll
    for (int r = 0; r < 16; r++)
        state_out[((size_t)(b*Hh + h)*DK + sub*16 + r) * DV + c] = S[r];
}

// ---------------------------------------------------------------------------
// SwiGLU: act = silu(gy[:, :I]) * gy[:, I:]
// ---------------------------------------------------------------------------
__global__ void swiglu_kernel(const float* __restrict__ gy, float* __restrict__ act) {
    int idx = blockIdx.x * blockDim.x + threadIdx.x;
    int row = idx / II;
    int i   = idx - row * II;
    float gate = gy[(size_t)row * (2*II) + i];
    float y    = gy[(size_t)row * (2*II) + II + i];
    act[idx] = gate / (1.0f + expf(-gate)) * y;
}

// ---------------------------------------------------------------------------
// launch
// ---------------------------------------------------------------------------
extern "C" void kernel_launch(void* const* d_in, const int* in_sizes, int n_in,
                              void* d_out, int out_size) {
    const float* x           = (const float*)d_in[0];
    const float* attn_norm_w = (const float*)d_in[1];
    const float* Wq          = (const float*)d_in[2];
    const float* Wk          = (const float*)d_in[3];
    const float* Wv          = (const float*)d_in[4];
    const float* cq          = (const float*)d_in[5];
    const float* ck          = (const float*)d_in[6];
    const float* cv          = (const float*)d_in[7];
    const float* Wb          = (const float*)d_in[8];
    const float* Wa          = (const float*)d_in[9];
    const float* dt_bias     = (const float*)d_in[10];
    const float* A_log       = (const float*)d_in[11];
    const float* o_norm_w    = (const float*)d_in[12];
    const float* Wo          = (const float*)d_in[13];
    const float* mlp_norm_w  = (const float*)d_in[14];
    const float* Wg          = (const float*)d_in[15];
    const float* Wd          = (const float*)d_in[16];
    float* out = (float*)d_out;

    float *h, *qpre, *kpre, *vpre, *q, *k, *v, *beta, *gg, *o, *h2, *h3, *gy, *act;
    cudaGetSymbolAddress((void**)&h,    g_h);
    cudaGetSymbolAddress((void**)&qpre, g_qpre);
    cudaGetSymbolAddress((void**)&kpre, g_kpre);
    cudaGetSymbolAddress((void**)&vpre, g_vpre);
    cudaGetSymbolAddress((void**)&q,    g_q);
    cudaGetSymbolAddress((void**)&k,    g_k);
    cudaGetSymbolAddress((void**)&v,    g_v);
    cudaGetSymbolAddress((void**)&beta, g_beta);
    cudaGetSymbolAddress((void**)&gg,   g_g);
    cudaGetSymbolAddress((void**)&o,    g_o);
    cudaGetSymbolAddress((void**)&h2,   g_h2);
    cudaGetSymbolAddress((void**)&h3,   g_h3);
    cudaGetSymbolAddress((void**)&gy,   g_gy);
    cudaGetSymbolAddress((void**)&act,  g_act);

    cudaFuncSetAttribute(betag_kernel,
                         cudaFuncAttributeMaxDynamicSharedMemorySize, BETAG_SMEM_BYTES);

    // 1. h = rmsnorm(x)
    rmsnorm_kernel<<<ROWS, 256>>>(x, attn_norm_w, h);

    // 2. q/k/v projections (one batched launch)
    dim3 gqkv(Dd/GBN, ROWS/GBM, 3);
    mma_gemm_qkv_kernel<<<gqkv, 256>>>(h, Wq, Wk, Wv, qpre, kpre, vpre, Dd, Dd);

    // 3. conv + silu (+ fused l2norm for q,k), one launch
    conv_fused3_kernel<<<dim3(ROWS, 3), 256>>>(qpre, cq, q, kpre, ck, k, vpre, cv, v);

    // 4. beta / g (register row-blocked)
    betag_kernel<<<BETAG_BLOCKS, 256, BETAG_SMEM_BYTES>>>(h, Wb, Wa, dt_bias, A_log, beta, gg);

    // 5. delta-rule scan (writes o and final state)
    scan_kernel<<<dim3(Hh, Bb), 256>>>(q, k, v, beta, gg, o, out + (size_t)ROWS*Dd);

    // 6. per-head output RMSNorm
    o_rmsnorm_kernel<<<(ROWS*Hh)/8, 256>>>(o, o_norm_w);

    // 7. attn projection + residual
    dim3 g1024(Dd/GBN, ROWS/GBM);
    mma_gemm_kernel<<<g1024, 256>>>(o, Wo, x, h2, Dd, Dd);

    // 8. MLP
    rmsnorm_kernel<<<ROWS, 256>>>(h2, mlp_norm_w, h3);
    dim3 gwg((2*II)/GBN, ROWS/GBM);
    mma_gemm_kernel<<<gwg, 256>>>(h3, Wg, nullptr, gy, 2*II, Dd);
    swiglu_kernel<<<(ROWS*II)/256, 256>>>(gy, act);
    mma_gemm_kernel<<<g1024, 256>>>(act, Wd, h2, out, Dd, II);
}

// round 11
// speedup vs baseline: 1.2792x; 1.1354x over previous
#include <cuda_runtime.h>
#include <cuda_fp16.h>
#include <math.h>
#include <stdint.h>

// ---------------------------------------------------------------------------
// Problem constants
// ---------------------------------------------------------------------------
#define Bb   4
#define Tt   1024
#define Dd   1024
#define Hh   16
#define DK   64
#define DV   64
#define II   2816
#define EPSf 1e-6f
#define ROWS (Bb*Tt)              // 4096

// ---------------------------------------------------------------------------
// Scratch (static device memory; no allocations allowed)
// ---------------------------------------------------------------------------
__device__ float g_h   [ROWS*Dd];      // rmsnorm(x)
__device__ float g_qpre[ROWS*Dd];
__device__ float g_kpre[ROWS*Dd];
__device__ float g_vpre[ROWS*Dd];
__device__ float g_q   [ROWS*Dd];
__device__ float g_k   [ROWS*Dd];
__device__ float g_v   [ROWS*Dd];
__device__ float g_beta[ROWS*Hh];
__device__ float g_g   [ROWS*Hh];
__device__ float g_o   [ROWS*Dd];      // attn output per head
__device__ float g_h2  [ROWS*Dd];      // x + attn_out
__device__ float g_h3  [ROWS*Dd];      // rmsnorm(h2)
__device__ float g_gy  [ROWS*2*II];    // h3 @ Wg
__device__ float g_act [ROWS*II];      // silu(gate)*y

// ---------------------------------------------------------------------------
// RMSNorm over D=1024, one block (256 thr) per row
// ---------------------------------------------------------------------------
__global__ void rmsnorm_kernel(const float* __restrict__ x, const float* __restrict__ w,
                               float* __restrict__ out) {
    int row = blockIdx.x;
    const float4* xr = (const float4*)(x + (size_t)row * Dd);
    float4 v = xr[threadIdx.x];
    float ss = v.x*v.x + v.y*v.y + v.z*v.z + v.w*v.w;
    #pragma unroll
    for (int m = 16; m >= 1; m >>= 1) ss += __shfl_xor_sync(0xffffffffu, ss, m);
    __shared__ float wsum[8];
    if ((threadIdx.x & 31) == 0) wsum[threadIdx.x >> 5] = ss;
    __syncthreads();
    float tot = wsum[0]+wsum[1]+wsum[2]+wsum[3]+wsum[4]+wsum[5]+wsum[6]+wsum[7];
    float r = rsqrtf(tot * (1.0f/Dd) + EPSf);
    float4 wv = ((const float4*)w)[threadIdx.x];
    float4 o;
    o.x = v.x*r*wv.x; o.y = v.y*r*wv.y; o.z = v.z*r*wv.z; o.w = v.w*r*wv.w;
    ((float4*)(out + (size_t)row * Dd))[threadIdx.x] = o;
}

// ---------------------------------------------------------------------------
// FP16 tensor-core GEMM: C[M,N] = A[M,K] @ B[K,N] (+addsrc), fp32 accumulate.
// BM=128 BN=128 BK=32, 256 threads (8 warps, 2x4), warp tile 64x32,
// mma.sync.m16n8k16.f16, ldmatrix fragment loads, double-buffered smem.
// A smem: 128 rows x 32 halfs, stride 40 halfs (80B) -> conflict-free ldmatrix.
// B smem: 32 rows x 128 halfs, stride 136 halfs (272B) -> conflict-free.
// ---------------------------------------------------------------------------
#define GBM 128
#define GBN 128
#define GBK 32
#define A_ROW_H 40
#define B_ROW_H 136

__device__ __forceinline__ uint32_t h2u(__half2 h) { return *(uint32_t*)&h; }

__device__ __forceinline__ void mma_f16(float& c0, float& c1, float& c2, float& c3,
                                        uint32_t a0, uint32_t a1, uint32_t a2, uint32_t a3,
                                        uint32_t b0, uint32_t b1) {
    asm volatile(
        "mma.sync.aligned.m16n8k16.row.col.f32.f16.f16.f32 "
        "{%0,%1,%2,%3}, {%4,%5,%6,%7}, {%8,%9}, {%0,%1,%2,%3};"
        : "+f"(c0), "+f"(c1), "+f"(c2), "+f"(c3)
        : "r"(a0), "r"(a1), "r"(a2), "r"(a3), "r"(b0), "r"(b1));
}

__device__ __forceinline__ void ldsm_x4(uint32_t* r, uint32_t addr) {
    asm volatile("ldmatrix.sync.aligned.m8n8.x4.shared.b16 {%0,%1,%2,%3}, [%4];"
                 : "=r"(r[0]), "=r"(r[1]), "=r"(r[2]), "=r"(r[3]) : "r"(addr));
}
__device__ __forceinline__ void ldsm_x2t(uint32_t* r, uint32_t addr) {
    asm volatile("ldmatrix.sync.aligned.m8n8.x2.trans.shared.b16 {%0,%1}, [%2];"
                 : "=r"(r[0]), "=r"(r[1]) : "r"(addr));
}

__device__ __forceinline__ void cvt_f4_h2(const float4& v, uint2& o) {
    __half2 p0 = __floats2half2_rn(v.x, v.y);
    __half2 p1 = __floats2half2_rn(v.z, v.w);
    o.x = h2u(p0); o.y = h2u(p1);
}

__device__ __forceinline__ void mma_gemm_body(
    const float* __restrict__ A, const float* __restrict__ B,
    const float* __restrict__ addsrc, float* __restrict__ C,
    int N, int Kd, int bm, int bn) {
    __shared__ __align__(16) __half As[2][128*A_ROW_H];
    __shared__ __align__(16) __half Bs[2][32*B_ROW_H];

    int tid = threadIdx.x;
    int lane = tid & 31;
    int w    = tid >> 5;
    int lq = lane >> 2;
    int lr = lane & 3;
    int wm = w >> 2;            // 0..1 -> M offset wm*64
    int wn = w & 3;             // 0..3 -> N offset wn*32

    // A staging: thread -> (row, 16-col half)
    int a_row = tid >> 1;
    int a_h16 = tid & 1;
    const float* Ag = A + (size_t)(bm + a_row) * Kd + a_h16*16;
    int a_soff = a_row*A_ROW_H + a_h16*16;

    // B staging: thread -> (k row, 16-col group)
    int b_k  = tid >> 3;
    int b_n0 = (tid & 7) * 16;
    const float* Bg = B + (size_t)b_k * N + bn + b_n0;
    int b_soff = b_k*B_ROW_H + b_n0;

    float acc[4][4][4];
    #pragma unroll
    for (int mi = 0; mi < 4; mi++)
        #pragma unroll
        for (int ni = 0; ni < 4; ni++)
            #pragma unroll
            for (int r = 0; r < 4; r++) acc[mi][ni][r] = 0.0f;

    int nch = Kd / GBK;

    uint2 arh[4], brh[4];
    #pragma unroll
    for (int i = 0; i < 4; i++) { cvt_f4_h2(*(const float4*)(Ag + 4*i), arh[i]); }
    #pragma unroll
    for (int i = 0; i < 4; i++) { cvt_f4_h2(*(const float4*)(Bg + 4*i), brh[i]); }

    #pragma unroll
    for (int i = 0; i < 4; i++) {
        *(uint2*)&As[0][a_soff + 4*i] = arh[i];
        *(uint2*)&Bs[0][b_soff + 4*i] = brh[i];
    }
    __syncthreads();

    for (int ch = 0; ch < nch; ch++) {
        int s = ch & 1;
        if (ch + 1 < nch) {
            const float* Agn = Ag + (ch + 1) * GBK;
            const float* Bgn = Bg + (size_t)(ch + 1) * GBK * N;
            #pragma unroll
            for (int i = 0; i < 4; i++) cvt_f4_h2(*(const float4*)(Agn + 4*i), arh[i]);
            #pragma unroll
            for (int i = 0; i < 4; i++) cvt_f4_h2(*(const float4*)(Bgn + 4*i), brh[i]);
        }

        #pragma unroll
        for (int ksi = 0; ksi < 2; ksi++) {
            uint32_t af[4][4];
            #pragma unroll
            for (int mi = 0; mi < 4; mi++) {
                int r = wm*64 + mi*16 + (lane & 15);
                uint32_t ad = (uint32_t)__cvta_generic_to_shared(
                    &As[s][r*A_ROW_H + ksi*16 + (lane >> 4)*8]);
                ldsm_x4(af[mi], ad);
            }
            uint32_t bf[4][2];
            #pragma unroll
            for (int ni = 0; ni < 4; ni++) {
                int kr = ksi*16 + (lane & 15);
                uint32_t ad = (uint32_t)__cvta_generic_to_shared(
                    &Bs[s][kr*B_ROW_H + wn*32 + ni*8]);
                ldsm_x2t(bf[ni], ad);
            }
            #pragma unroll
            for (int mi = 0; mi < 4; mi++)
                #pragma unroll
                for (int ni = 0; ni < 4; ni++)
                    mma_f16(acc[mi][ni][0], acc[mi][ni][1], acc[mi][ni][2], acc[mi][ni][3],
                            af[mi][0], af[mi][1], af[mi][2], af[mi][3],
                            bf[ni][0], bf[ni][1]);
        }

        if (ch + 1 < nch) {
            int s1 = s ^ 1;
            #pragma unroll
            for (int i = 0; i < 4; i++) {
                *(uint2*)&As[s1][a_soff + 4*i] = arh[i];
                *(uint2*)&Bs[s1][b_soff + 4*i] = brh[i];
            }
            __syncthreads();
        }
    }

    // epilogue (same fragment layout as m16n8k8: rows lq/lq+8, cols 2lr,2lr+1)
    #pragma unroll
    for (int mi = 0; mi < 4; mi++) {
        int r0 = bm + wm*64 + mi*16 + lq;
        #pragma unroll
        for (int ni = 0; ni < 4; ni++) {
            int col = bn + wn*32 + ni*8 + 2*lr;
            float2 v0 = make_float2(acc[mi][ni][0], acc[mi][ni][1]);
            float2 v1 = make_float2(acc[mi][ni][2], acc[mi][ni][3]);
            if (addsrc) {
                float2 s0 = *(const float2*)(addsrc + (size_t)r0 * N + col);
                float2 s1 = *(const float2*)(addsrc + (size_t)(r0+8) * N + col);
                v0.x += s0.x; v0.y += s0.y; v1.x += s1.x; v1.y += s1.y;
            }
            *(float2*)(C + (size_t)r0 * N + col) = v0;
            *(float2*)(C + (size_t)(r0+8) * N + col) = v1;
        }
    }
}

__global__ __launch_bounds__(256, 2) void mma_gemm_kernel(
    const float* __restrict__ A, const float* __restrict__ B,
    const float* __restrict__ addsrc, float* __restrict__ C,
    int N, int Kd) {
    mma_gemm_body(A, B, addsrc, C, N, Kd, blockIdx.y * GBM, blockIdx.x * GBN);
}

__global__ __launch_bounds__(256, 2) void mma_gemm_qkv_kernel(
    const float* __restrict__ A,
    const float* __restrict__ B0, const float* __restrict__ B1, const float* __restrict__ B2,
    float* __restrict__ C0, float* __restrict__ C1, float* __restrict__ C2,
    int N, int Kd) {
    const float* B = (blockIdx.z == 0) ? B0 : ((blockIdx.z == 1) ? B1 : B2);
    float*       C = (blockIdx.z == 0) ? C0 : ((blockIdx.z == 1) ? C1 : C2);
    mma_gemm_body(A, B, nullptr, C, N, Kd, blockIdx.y * GBM, blockIdx.x * GBN);
}

// ---------------------------------------------------------------------------
// Fused causal depthwise conv1d (K=4) + SiLU + optional per-head L2 norm.
// ---------------------------------------------------------------------------
__global__ void conv_fused3_kernel(
    const float* __restrict__ xq, const float* __restrict__ wq, float* __restrict__ oq,
    const float* __restrict__ xk, const float* __restrict__ wk, float* __restrict__ ok,
    const float* __restrict__ xv, const float* __restrict__ wv, float* __restrict__ ov) {
    int which = blockIdx.y;
    const float* xin = (which == 0) ? xq : ((which == 1) ? xk : xv);
    const float* w   = (which == 0) ? wq : ((which == 1) ? wk : wv);
    float* out       = (which == 0) ? oq : ((which == 1) ? ok : ov);
    float scale = (which == 0) ? 0.125f : 1.0f;
    int do_l2   = (which != 2);

    int row = blockIdx.x;
    int t = row & (Tt - 1);
    int c4 = threadIdx.x * 4;
    size_t base = (size_t)row * Dd + c4;

    float4 x0 = *(const float4*)(xin + base);
    float4 x1 = (t >= 1) ? *(const float4*)(xin + base - Dd)   : make_float4(0,0,0,0);
    float4 x2 = (t >= 2) ? *(const float4*)(xin + base - 2*Dd) : make_float4(0,0,0,0);
    float4 x3 = (t >= 3) ? *(const float4*)(xin + base - 3*Dd) : make_float4(0,0,0,0);

    float y[4];
    #pragma unroll
    for (int j = 0; j < 4; j++) {
        float4 w4 = ((const float4*)w)[c4 + j];
        float a = (&x0.x)[j]*w4.w + (&x1.x)[j]*w4.z + (&x2.x)[j]*w4.y + (&x3.x)[j]*w4.x;
        y[j] = a / (1.0f + expf(-a));
    }

    if (do_l2) {
        float ss = y[0]*y[0] + y[1]*y[1] + y[2]*y[2] + y[3]*y[3];
        #pragma unroll
        for (int m = 8; m >= 1; m >>= 1) ss += __shfl_xor_sync(0xffffffffu, ss, m);
        float r = rsqrtf(ss + EPSf) * scale;
        #pragma unroll
        for (int j = 0; j < 4; j++) y[j] *= r;
    }
    *(float4*)(out + base) = make_float4(y[0], y[1], y[2], y[3]);
}

// ---------------------------------------------------------------------------
// Per-(b,t,h) RMSNorm over DV=64 with weight. In place.
// ---------------------------------------------------------------------------
__global__ void o_rmsnorm_kernel(float* __restrict__ o, const float* __restrict__ w) {
    int gidx = blockIdx.x * 8 + (threadIdx.x >> 5);
    int lane = threadIdx.x & 31;
    size_t base = (size_t)gidx * 64;
    float a = o[base + lane], b = o[base + 32 + lane];
    float ss = a*a + b*b;
    #pragma unroll
    for (int m = 16; m >= 1; m >>= 1) ss += __shfl_xor_sync(0xffffffffu, ss, m);
    float r = rsqrtf(ss * (1.0f/64.0f) + EPSf);
    o[base + lane]      = a * r * w[lane];
    o[base + 32 + lane] = b * r * w[lane + 32];
}

// ---------------------------------------------------------------------------
// beta / g projections v3: 128 blocks x 32 rows (2 passes of 16).
// Weights staged once (128KB smem); 16 rows of h staged per pass (64KB);
// 16 rows of register accumulators per thread (row-level ILP).
// ---------------------------------------------------------------------------
#define BETAG_BLOCKS 128
#define BETAG_RPB 32
#define BETAG_PASS 16
#define BETAG_SMEM_FLTS (2*Dd*Hh + BETAG_PASS*Dd)
#define BETAG_SMEM_BYTES (BETAG_SMEM_FLTS*4)

__global__ __launch_bounds__(256) void betag_kernel(
    const float* __restrict__ h,
    const float* __restrict__ Wb, const float* __restrict__ Wa,
    const float* __restrict__ dt_bias, const float* __restrict__ A_log,
    float* __restrict__ beta, float* __restrict__ g) {
    extern __shared__ float bsm[];
    float* wbs = bsm;
    float* was = bsm + Dd*Hh;
    float* hst = bsm + 2*Dd*Hh;

    int tid = threadIdx.x;
    int hh  = tid & 15;
    int grp = tid >> 4;
    int row0 = blockIdx.x * BETAG_RPB;

    for (int i = tid; i < 8192; i += 256) {
        float4 vb = ((const float4*)Wb)[i & 4095];
        if (i < 4096) ((float4*)wbs)[i] = vb;
        else          ((float4*)was)[i - 4096] = ((const float4*)Wa)[i - 4096];
    }

    for (int p = 0; p < 2; p++) {
        int prow0 = row0 + p * BETAG_PASS;
        __syncthreads();
        for (int i = tid; i < 4096; i += 256)
            ((float4*)hst)[i] = ((const float4*)(h + (size_t)prow0 * Dd))[i];
        __syncthreads();

        float sb[BETAG_PASS], sa[BETAG_PASS];
        #pragma unroll
        for (int r = 0; r < BETAG_PASS; r++) { sb[r] = 0.0f; sa[r] = 0.0f; }

        #pragma unroll 4
        for (int j = 0; j < 64; j++) {
            int d = j*16 + grp;
            float wb = wbs[d*Hh + hh];
            float wa = was[d*Hh + hh];
            #pragma unroll
            for (int r = 0; r < BETAG_PASS; r++) {
                float hv = hst[r*Dd + d];
                sb[r] += hv * wb;
                sa[r] += hv * wa;
            }
        }
        __syncthreads();

        #pragma unroll
        for (int r = 0; r < BETAG_PASS; r++) {
            hst[(r<<9) + (grp<<4) + hh]       = sb[r];
            hst[(r<<9) + 256 + (grp<<4) + hh] = sa[r];
        }
        __syncthreads();

        #pragma unroll
        for (int u = 0; u < 2; u++) {
            int idx = tid + u*256;
            int r2    = idx >> 5;
            int which = (idx >> 4) & 1;
            int hh2   = idx & 15;
            const float* rp = hst + (r2<<9) + which*256 + hh2;
            float s = 0.0f;
            #pragma unroll
            for (int gg2 = 0; gg2 < 16; gg2++) s += rp[gg2*16];
            int row = prow0 + r2;
            if (which == 0) {
                beta[row*Hh + hh2] = 2.0f / (1.0f + expf(-s));
            } else {
                float xg = s + dt_bias[hh2];
                float sp = (xg > 15.0f) ? xg : log1pf(expf(xg));
                g[row*Hh + hh2] = -expf(A_log[hh2]) * sp;
            }
        }
    }
}

// ---------------------------------------------------------------------------
// Gated delta-rule scan with register prefetch + split reduction chains.
// ---------------------------------------------------------------------------
__device__ __forceinline__ float scan_load(const float* __restrict__ q,
                                           const float* __restrict__ k,
                                           const float* __restrict__ v,
                                           const float* __restrict__ beta,
                                           const float* __restrict__ g,
                                           int b, int h, int t, int tid) {
    size_t off = ((size_t)(b*Tt + t)) * 1024 + h * 64;
    if (tid < 64)  return k[off + tid];
    if (tid < 128) return q[off + tid - 64];
    if (tid < 192) return v[off + tid - 128];
    if (tid == 192) return beta[(size_t)(b*Tt + t)*Hh + h];
    return g[(size_t)(b*Tt + t)*Hh + h];
}

__global__ __launch_bounds__(256) void scan_kernel(
    const float* __restrict__ q, const float* __restrict__ k, const float* __restrict__ v,
    const float* __restrict__ beta, const float* __restrict__ g,
    float* __restrict__ o, float* __restrict__ state_out) {
    int h = blockIdx.x, b = blockIdx.y;
    int tid = threadIdx.x;
    int c   = tid >> 2;
    int sub = tid & 3;

    __shared__ __align__(16) float sh[2][200];

    float S[16];
    #pragma unroll
    for (int r = 0; r < 16; r++) S[r] = 0.0f;

    float rv = (tid < 194) ? scan_load(q, k, v, beta, g, b, h, 0, tid) : 0.0f;

    for (int t = 0; t < Tt; t++) {
        float* buf = sh[t & 1];
        if (tid < 194) buf[tid] = rv;
        __syncthreads();
        if (t + 1 < Tt && tid < 194)
            rv = scan_load(q, k, v, beta, g, b, h, t + 1, tid);

        float eg = expf(buf[193]);
        float bt = buf[192];

        const float4* kp4 = (const float4*)(buf + sub*16);
        const float4* qp4 = (const float4*)(buf + 64 + sub*16);
        float kr[16], qr[16];
        #pragma unroll
        for (int rr = 0; rr < 4; rr++) {
            float4 kv4 = kp4[rr];
            kr[rr*4+0] = kv4.x; kr[rr*4+1] = kv4.y; kr[rr*4+2] = kv4.z; kr[rr*4+3] = kv4.w;
            float4 qv4 = qp4[rr];
            qr[rr*4+0] = qv4.x; qr[rr*4+1] = qv4.y; qr[rr*4+2] = qv4.z; qr[rr*4+3] = qv4.w;
        }

        float k0 = 0.0f, k1 = 0.0f, k2 = 0.0f, k3 = 0.0f;
        #pragma unroll
        for (int r4 = 0; r4 < 4; r4++) {
            S[4*r4+0] *= eg; k0 += kr[4*r4+0] * S[4*r4+0];
            S[4*r4+1] *= eg; k1 += kr[4*r4+1] * S[4*r4+1];
            S[4*r4+2] *= eg; k2 += kr[4*r4+2] * S[4*r4+2];
            S[4*r4+3] *= eg; k3 += kr[4*r4+3] * S[4*r4+3];
        }
        float kvp = (k0 + k1) + (k2 + k3);
        kvp += __shfl_xor_sync(0xffffffffu, kvp, 1);
        kvp += __shfl_xor_sync(0xffffffffu, kvp, 2);

        float delta = (buf[128 + c] - kvp) * bt;

        float o0 = 0.0f, o1 = 0.0f, o2 = 0.0f, o3 = 0.0f;
        #pragma unroll
        for (int r4 = 0; r4 < 4; r4++) {
            S[4*r4+0] += kr[4*r4+0] * delta; o0 += qr[4*r4+0] * S[4*r4+0];
            S[4*r4+1] += kr[4*r4+1] * delta; o1 += qr[4*r4+1] * S[4*r4+1];
            S[4*r4+2] += kr[4*r4+2] * delta; o2 += qr[4*r4+2] * S[4*r4+2];
            S[4*r4+3] += kr[4*r4+3] * delta; o3 += qr[4*r4+3] * S[4*r4+3];
        }
        float op = (o0 + o1) + (o2 + o3);
        op += __shfl_xor_sync(0xffffffffu, op, 1);
        op += __shfl_xor_sync(0xffffffffu, op, 2);
        if (sub == 0)
            o[((size_t)(b*Tt + t)*Hh + h) * DV + c] = op;
    }

    #pragma unroll
    for (int r = 0; r < 16; r++)
        state_out[((size_t)(b*Hh + h)*DK + sub*16 + r) * DV + c] = S[r];
}

// ---------------------------------------------------------------------------
// SwiGLU: act = silu(gy[:, :I]) * gy[:, I:]
// ---------------------------------------------------------------------------
__global__ void swiglu_kernel(const float* __restrict__ gy, float* __restrict__ act) {
    int idx = blockIdx.x * blockDim.x + threadIdx.x;
    int row = idx / II;
    int i   = idx - row * II;
    float gate = gy[(size_t)row * (2*II) + i];
    float y    = gy[(size_t)row * (2*II) + II + i];
    act[idx] = gate / (1.0f + expf(-gate)) * y;
}

// ---------------------------------------------------------------------------
// launch
// ---------------------------------------------------------------------------
extern "C" void kernel_launch(void* const* d_in, const int* in_sizes, int n_in,
                              void* d_out, int out_size) {
    const float* x           = (const float*)d_in[0];
    const float* attn_norm_w = (const float*)d_in[1];
    const float* Wq          = (const float*)d_in[2];
    const float* Wk          = (const float*)d_in[3];
    const float* Wv          = (const float*)d_in[4];
    const float* cq          = (const float*)d_in[5];
    const float* ck          = (const float*)d_in[6];
    const float* cv          = (const float*)d_in[7];
    const float* Wb          = (const float*)d_in[8];
    const float* Wa          = (const float*)d_in[9];
    const float* dt_bias     = (const float*)d_in[10];
    const float* A_log       = (const float*)d_in[11];
    const float* o_norm_w    = (const float*)d_in[12];
    const float* Wo          = (const float*)d_in[13];
    const float* mlp_norm_w  = (const float*)d_in[14];
    const float* Wg          = (const float*)d_in[15];
    const float* Wd          = (const float*)d_in[16];
    float* out = (float*)d_out;

    float *h, *qpre, *kpre, *vpre, *q, *k, *v, *beta, *gg, *o, *h2, *h3, *gy, *act;
    cudaGetSymbolAddress((void**)&h,    g_h);
    cudaGetSymbolAddress((void**)&qpre, g_qpre);
    cudaGetSymbolAddress((void**)&kpre, g_kpre);
    cudaGetSymbolAddress((void**)&vpre, g_vpre);
    cudaGetSymbolAddress((void**)&q,    g_q);
    cudaGetSymbolAddress((void**)&k,    g_k);
    cudaGetSymbolAddress((void**)&v,    g_v);
    cudaGetSymbolAddress((void**)&beta, g_beta);
    cudaGetSymbolAddress((void**)&gg,   g_g);
    cudaGetSymbolAddress((void**)&o,    g_o);
    cudaGetSymbolAddress((void**)&h2,   g_h2);
    cudaGetSymbolAddress((void**)&h3,   g_h3);
    cudaGetSymbolAddress((void**)&gy,   g_gy);
    cudaGetSymbolAddress((void**)&act,  g_act);

    cudaFuncSetAttribute(betag_kernel,
                         cudaFuncAttributeMaxDynamicSharedMemorySize, BETAG_SMEM_BYTES);

    // 1. h = rmsnorm(x)
    rmsnorm_kernel<<<ROWS, 256>>>(x, attn_norm_w, h);

    // 2. q/k/v projections (one batched launch, fp16 tensor cores)
    dim3 gqkv(Dd/GBN, ROWS/GBM, 3);
    mma_gemm_qkv_kernel<<<gqkv, 256>>>(h, Wq, Wk, Wv, qpre, kpre, vpre, Dd, Dd);

    // 3. conv + silu (+ fused l2norm for q,k), one launch
    conv_fused3_kernel<<<dim3(ROWS, 3), 256>>>(qpre, cq, q, kpre, ck, k, vpre, cv, v);

    // 4. beta / g
    betag_kernel<<<BETAG_BLOCKS, 256, BETAG_SMEM_BYTES>>>(h, Wb, Wa, dt_bias, A_log, beta, gg);

    // 5. delta-rule scan (writes o and final state)
    scan_kernel<<<dim3(Hh, Bb), 256>>>(q, k, v, beta, gg, o, out + (size_t)ROWS*Dd);

    // 6. per-head output RMSNorm
    o_rmsnorm_kernel<<<(ROWS*Hh)/8, 256>>>(o, o_norm_w);

    // 7. attn projection + residual
    dim3 g1024(Dd/GBN, ROWS/GBM);
    mma_gemm_kernel<<<g1024, 256>>>(o, Wo, x, h2, Dd, Dd);

    // 8. MLP
    rmsnorm_kernel<<<ROWS, 256>>>(h2, mlp_norm_w, h3);
    dim3 gwg((2*II)/GBN, ROWS/GBM);
    mma_gemm_kernel<<<gwg, 256>>>(h3, Wg, nullptr, gy, 2*II, Dd);
    swiglu_kernel<<<(ROWS*II)/256, 256>>>(gy, act);
    mma_gemm_kernel<<<g1024, 256>>>(act, Wd, h2, out, Dd, II);
}